// round 6
// baseline (speedup 1.0000x reference)
#include <cuda_runtime.h>
#include <math.h>
#include <stdint.h>

#define FULL 0xffffffffu
#define MAXN 50000
#define MAXE 400000

// Scratch (device globals; no allocation allowed)
__device__ float  f_buf[MAXN * 128];      // per-node lin1 features [f0|f1x|f1y|f1z]
// per-node accum: [node][ A-part: u*4 -> (mA,mD,mBx,mCx) | B-part: u*4 -> (mBy,mCy,mBz,mCz) ]
__device__ float4 n_buf4[MAXN * 64];
__device__ int    deg_buf[MAXN];
__device__ int    cursor_buf[MAXN];
__device__ int    csr_eid[MAXE];

__host__ __device__ __forceinline__ int divup(int a, int b) { return (a + b - 1) / b; }

static __device__ __forceinline__ void red_v4(float* p, float a, float b, float c, float d) {
    asm volatile("red.global.add.v4.f32 [%0], {%1,%2,%3,%4};"
                 :: "l"(p), "f"(a), "f"(b), "f"(c), "f"(d) : "memory");
}
static __device__ __forceinline__ unsigned long long pack2(float lo, float hi) {
    unsigned long long r;
    asm("mov.b64 %0, {%1,%2};" : "=l"(r) : "f"(lo), "f"(hi));
    return r;
}
static __device__ __forceinline__ void fma2(unsigned long long& acc, unsigned long long a, unsigned long long b) {
    asm("fma.rn.f32x2 %0, %1, %2, %0;" : "+l"(acc) : "l"(a), "l"(b));
}
static __device__ __forceinline__ float2 unpack2(unsigned long long v) {
    float2 r;
    asm("mov.b64 {%0,%1}, %2;" : "=f"(r.x), "=f"(r.y) : "l"(v));
    return r;
}
static __device__ __forceinline__ uint32_t to_tf32(float f) {
    uint32_t r; asm("cvt.rna.tf32.f32 %0, %1;" : "=r"(r) : "f"(f)); return r;
}

// ---------------------------------------------------------------------------
// CSR build: histogram -> scan -> scatter
// ---------------------------------------------------------------------------
__global__ __launch_bounds__(256) void hist_kernel(const int* __restrict__ edge_dst, int E) {
    int e = blockIdx.x * blockDim.x + threadIdx.x;
    if (e < E) atomicAdd(&deg_buf[edge_dst[e]], 1);
}

__global__ __launch_bounds__(1024) void scan_kernel(int N) {
    __shared__ int part[1024];
    int t = threadIdx.x;
    int C = divup(N, 1024);
    int start = t * C;
    int end = min(start + C, N);
    int s = 0;
    for (int i = start; i < end; i++) s += deg_buf[i];
    part[t] = s;
    __syncthreads();
    // Hillis-Steele inclusive scan
    for (int off = 1; off < 1024; off <<= 1) {
        int v = 0;
        if (t >= off) v = part[t - off];
        __syncthreads();
        part[t] += v;
        __syncthreads();
    }
    int run = (t == 0) ? 0 : part[t - 1];
    for (int i = start; i < end; i++) {
        cursor_buf[i] = run;
        run += deg_buf[i];
    }
}

__global__ __launch_bounds__(256) void scatter_kernel(const int* __restrict__ edge_dst, int E) {
    int e = blockIdx.x * blockDim.x + threadIdx.x;
    if (e < E) {
        int pos = atomicAdd(&cursor_buf[edge_dst[e]], 1);
        csr_eid[pos] = e;
    }
}

// ---------------------------------------------------------------------------
// Kernel 1: node pre-pass. One warp per 2 nodes; x broadcast via smem v4.
// ---------------------------------------------------------------------------
__global__ __launch_bounds__(256) void node_pre_kernel(
    const float* __restrict__ node_input,
    const float* __restrict__ node_attr,
    const float* __restrict__ w_sc0,
    const float* __restrict__ w_sc1,
    const float* __restrict__ w_l0,
    const float* __restrict__ w_l1,
    float* __restrict__ out_node,
    int N)
{
    __shared__ float s0[1024], s1[1024], s2[1024], s3[1024];
    __shared__ float4 sx[8][2][32];
    for (int i = threadIdx.x; i < 1024; i += blockDim.x) {
        s0[i] = w_sc0[i]; s1[i] = w_sc1[i]; s2[i] = w_l0[i]; s3[i] = w_l1[i];
    }
    __syncthreads();

    int warp = (blockIdx.x * blockDim.x + threadIdx.x) >> 5;
    int wid  = (threadIdx.x >> 5);
    int lane = threadIdx.x & 31;
    int nA = warp * 2;
    int nB = nA + 1;
    if (nA >= N) return;
    bool hasB = (nB < N);

    {
        const float* rowA = node_input + (size_t)nA * 128;
        sx[wid][0][lane] = make_float4(rowA[lane], rowA[32 + 3 * lane],
                                       rowA[33 + 3 * lane], rowA[34 + 3 * lane]);
        if (hasB) {
            const float* rowB = node_input + (size_t)nB * 128;
            sx[wid][1][lane] = make_float4(rowB[lane], rowB[32 + 3 * lane],
                                           rowB[33 + 3 * lane], rowB[34 + 3 * lane]);
        }
    }
    float aA = node_attr[nA];
    float aB = hasB ? node_attr[nB] : 0.f;
    __syncwarp();

    float scA0 = 0.f, fA0 = 0.f, scA1x = 0.f, scA1y = 0.f, scA1z = 0.f, fA1x = 0.f, fA1y = 0.f, fA1z = 0.f;
    float scB0 = 0.f, fB0 = 0.f, scB1x = 0.f, scB1y = 0.f, scB1z = 0.f, fB1x = 0.f, fB1y = 0.f, fB1z = 0.f;

#pragma unroll
    for (int u = 0; u < 32; u++) {
        float wsc0 = s0[u * 32 + lane];
        float wsc1 = s1[u * 32 + lane];
        float wl0  = s2[u * 32 + lane];
        float wl1  = s3[u * 32 + lane];

        float4 xa = sx[wid][0][u];  // LDS.128 broadcast
        scA0  += xa.x * wsc0;  fA0  += xa.x * wl0;
        scA1x += xa.y * wsc1;  scA1y += xa.z * wsc1;  scA1z += xa.w * wsc1;
        fA1x  += xa.y * wl1;   fA1y  += xa.z * wl1;   fA1z  += xa.w * wl1;

        float4 xb = sx[wid][1][u];
        scB0  += xb.x * wsc0;  fB0  += xb.x * wl0;
        scB1x += xb.y * wsc1;  scB1y += xb.z * wsc1;  scB1z += xb.w * wsc1;
        fB1x  += xb.y * wl1;   fB1y  += xb.z * wl1;   fB1z  += xb.w * wl1;
    }
    __syncwarp();

    const float s_in = 0.17677669529663687f; // 1/sqrt(32)
    float* st = (float*)&sx[wid][0][0];

    {
        float sA = aA * s_in;
        st[lane]          = scA0 * sA;
        st[32 + 3 * lane] = scA1x * sA;
        st[33 + 3 * lane] = scA1y * sA;
        st[34 + 3 * lane] = scA1z * sA;
        __syncwarp();
        ((float4*)(out_node + (size_t)nA * 128))[lane] = ((const float4*)st)[lane];
        __syncwarp();
        float* fb = f_buf + (size_t)nA * 128;
        fb[lane]      = fA0  * sA;
        fb[32 + lane] = fA1x * sA;
        fb[64 + lane] = fA1y * sA;
        fb[96 + lane] = fA1z * sA;
    }
    if (hasB) {
        float sB = aB * s_in;
        st[lane]          = scB0 * sB;
        st[32 + 3 * lane] = scB1x * sB;
        st[33 + 3 * lane] = scB1y * sB;
        st[34 + 3 * lane] = scB1z * sB;
        __syncwarp();
        ((float4*)(out_node + (size_t)nB * 128))[lane] = ((const float4*)st)[lane];
        __syncwarp();
        float* fb = f_buf + (size_t)nB * 128;
        fb[lane]      = fB0  * sB;
        fb[32 + lane] = fB1x * sB;
        fb[64 + lane] = fB1y * sB;
        fb[96 + lane] = fB1z * sB;
    }
}

// ---------------------------------------------------------------------------
// Kernel 2 (fused, CSR order): per block of 128 sorted-by-dst edges:
//   GEMM1: H = sin(ES@W1*0.25) (f32x2), GEMM2: W = H@W2*0.125 (tf32 mma),
//   message construction with register run-accumulation, flush-on-dst-change
//   via red.v4, 4 combined warp reductions for edge outputs.
// ---------------------------------------------------------------------------
#define EPAD 132
#define HP   68
#define SWS  134
// dynamic smem float offsets
#define OFF_EID  0
#define OFF_SRC  128
#define OFF_DST  256
#define OFF_EA   384          // float4[128] = 512 floats (16B aligned: 384*4=1536)
#define OFF_BF   896          // 8192 floats
#define OFF_REG  9088         // union region: 17152 floats
#define SMEM_FLOATS (9088 + 17152)

__global__ void __launch_bounds__(256, 2) edge_fused_kernel(
    const int*   __restrict__ edge_src,
    const int*   __restrict__ edge_dst,
    const float* __restrict__ edge_attr,
    const float* __restrict__ edge_scalars,
    const float* __restrict__ fc_w1,
    const float* __restrict__ fc_w2,
    const float* __restrict__ w_se0a,
    const float* __restrict__ w_se0b,
    const float* __restrict__ w_se1a,
    const float* __restrict__ w_se1b,
    float* __restrict__ out_edge,
    int E)
{
    extern __shared__ float sm[];
    int*    sEID = (int*)(sm + OFF_EID);
    int*    sSRC = (int*)(sm + OFF_SRC);
    int*    sDST = (int*)(sm + OFF_DST);
    float4* sEA  = (float4*)(sm + OFF_EA);
    float*  sBf  = sm + OFF_BF;
    float*  region = sm + OFF_REG;
    float* sW1  = region;                // 1024
    float* sEST = region + 1024;         // 16*132 = 2112 (k-major ES^T)
    float* sH   = region + 3136;         // 128*68 = 8704 (edge-major, tf32 bits)
    float* sW   = region;                // phase B: 128*134 = 17152

    int t = threadIdx.x;
    int e0 = blockIdx.x * 128;
    int lane = t & 31;
    int wwid = t >> 5;

    // ---- stage edge ids first (needed by gathers below) ----
    if (t < 128) {
        int eid = (e0 + t < E) ? csr_eid[e0 + t] : 0;
        sEID[t] = eid;
    }
    __syncthreads();

    // ---- stage per-edge metadata + W1 (scaled) + ES tile + B fragments ----
    if (t < 128) {
        int eid = sEID[t];
        sSRC[t] = edge_src[eid];
        sDST[t] = edge_dst[eid];
        sEA[t]  = ((const float4*)edge_attr)[eid];
    }
    {
        float4 v = ((const float4*)fc_w1)[t];
        v.x *= 0.25f; v.y *= 0.25f; v.z *= 0.25f; v.w *= 0.25f;
        ((float4*)sW1)[t] = v;
    }
#pragma unroll
    for (int r = 0; r < 2; r++) {
        int fidx = t + r * 256;     // 0..511 float4s of the ES tile
        int e = fidx >> 2;          // 0..127
        int k4 = fidx & 3;
        int eid = sEID[e];
        float4 v = ((const float4*)edge_scalars)[(size_t)eid * 4 + k4];
        sEST[(k4 * 4 + 0) * EPAD + e] = v.x;
        sEST[(k4 * 4 + 1) * EPAD + e] = v.y;
        sEST[(k4 * 4 + 2) * EPAD + e] = v.z;
        sEST[(k4 * 4 + 3) * EPAD + e] = v.w;
    }
    {
        uint32_t* sBfu = (uint32_t*)sBf;
#pragma unroll
        for (int rep = 0; rep < 32; rep++) {
            int idx = rep * 256 + t;        // 0..8191, coalesced gmem reads
            int n = idx & 127;
            int k = idx >> 7;
            float val = fc_w2[k * 128 + n] * 0.125f;
            int nt = n >> 3, ks = k >> 3, rb = (k >> 2) & 1;
            int ln = ((n & 7) << 2) | (k & 3);
            sBfu[(nt * 8 + ks) * 64 + ln * 2 + rb] = to_tf32(val);
        }
    }
    __syncthreads();

    // ---- GEMM1: thread tile = 4 edges (2 pairs, 64 apart) x 8 cols ----
    {
        int txe = t & 31;   // edge pairs at txe*2 and txe*2+64
        int tyc = t >> 5;   // cols tyc*8 + j
        unsigned long long acc[8][2];
#pragma unroll
        for (int j = 0; j < 8; j++) { acc[j][0] = 0ull; acc[j][1] = 0ull; }
#pragma unroll
        for (int k = 0; k < 16; k++) {
            unsigned long long a0 = *(const unsigned long long*)(sEST + k * EPAD + txe * 2);
            unsigned long long a1 = *(const unsigned long long*)(sEST + k * EPAD + txe * 2 + 64);
#pragma unroll
            for (int j = 0; j < 8; j++) {
                float b = sW1[k * 64 + tyc * 8 + j];
                unsigned long long bb = pack2(b, b);
                fma2(acc[j][0], a0, bb);
                fma2(acc[j][1], a1, bb);
            }
        }
        uint32_t* sHu = (uint32_t*)sH;
#pragma unroll
        for (int j = 0; j < 8; j++) {
            int col = tyc * 8 + j;
#pragma unroll
            for (int i = 0; i < 2; i++) {
                float2 v = unpack2(acc[j][i]);
                int e = txe * 2 + 64 * i;
                sHu[e * HP + col]       = to_tf32(__sinf(v.x));
                sHu[(e + 1) * HP + col] = to_tf32(__sinf(v.y));
            }
        }
    }
    __syncthreads();

    // ---- load A fragments (16 edges per warp, K=64 -> 8 ksteps) ----
    uint32_t afr[8][4];
    {
        const uint32_t* sHu = (const uint32_t*)sH;
        int er = wwid * 16 + (lane >> 2);
        int kl = lane & 3;
#pragma unroll
        for (int ks = 0; ks < 8; ks++) {
            int k0 = ks * 8 + kl;
            afr[ks][0] = sHu[er * HP + k0];
            afr[ks][1] = sHu[(er + 8) * HP + k0];
            afr[ks][2] = sHu[er * HP + k0 + 4];
            afr[ks][3] = sHu[(er + 8) * HP + k0 + 4];
        }
    }
    __syncthreads();   // sH dead; region becomes sW

    // ---- GEMM2: tf32 mma, warp computes 16 edges x 128 outs ----
    {
        const uint32_t* bf = (const uint32_t*)sBf;
        int er = wwid * 16 + (lane >> 2);
        int nb = (lane & 3) * 2;
#pragma unroll
        for (int nt = 0; nt < 16; nt++) {
            float c0 = 0.f, c1 = 0.f, c2 = 0.f, c3 = 0.f;
#pragma unroll
            for (int ks = 0; ks < 8; ks++) {
                uint2 b = *(const uint2*)(bf + (nt * 8 + ks) * 64 + lane * 2);
                asm volatile(
                    "mma.sync.aligned.m16n8k8.row.col.f32.tf32.tf32.f32 "
                    "{%0,%1,%2,%3},{%4,%5,%6,%7},{%8,%9},{%0,%1,%2,%3};"
                    : "+f"(c0), "+f"(c1), "+f"(c2), "+f"(c3)
                    : "r"(afr[ks][0]), "r"(afr[ks][1]), "r"(afr[ks][2]), "r"(afr[ks][3]),
                      "r"(b.x), "r"(b.y));
            }
            int n = nt * 8 + nb;
            *(float2*)(sW + er * SWS + n)       = make_float2(c0, c1);
            *(float2*)(sW + (er + 8) * SWS + n) = make_float2(c2, c3);
        }
    }
    __syncthreads();

    // ---- message phase: warp handles 16 consecutive CSR edges, batched by 4,
    //      register run-accumulation with flush on dst change ----
    float a0lo = w_se0a[lane],      a0hi = w_se0a[32 + lane];
    float b0lo = w_se0b[lane],      b0hi = w_se0b[32 + lane];
    float a1lo = w_se1a[lane],      a1hi = w_se1a[32 + lane];
    float b1lo = w_se1b[lane],      b1hi = w_se1b[32 + lane];

    const float INV_SQRT3 = 0.5773502691896258f;
    const float s_se   = 0.08838834764831845f;   // 1/sqrt(128)
    const float inv_nn = 0.35355339059327373f;   // 1/sqrt(8)
    const float sosc   = s_se * inv_nn;

    int lbase = wwid * 16;
    int nloc = E - (e0 + lbase);
    if (nloc > 16) nloc = 16;

    float acc0 = 0.f, acc1 = 0.f, acc2 = 0.f, acc3 = 0.f;
    float acc4 = 0.f, acc5 = 0.f, acc6 = 0.f, acc7 = 0.f;
    int run_dst = -1;

    if (nloc == 16) {
#pragma unroll 1
        for (int g = 0; g < 4; g++) {
            float4 eav[4];
            float g0v[4], g1xv[4], g1yv[4], g1zv[4];
            float wAv[4], wBv[4], wCv[4], wDv[4];
#pragma unroll
            for (int i = 0; i < 4; i++) {
                int el = lbase + g * 4 + i;
                int src = sSRC[el];
                eav[i] = sEA[el];
                const float* fr = f_buf + (size_t)src * 128;
                g0v[i]  = fr[lane];
                g1xv[i] = fr[32 + lane];
                g1yv[i] = fr[64 + lane];
                g1zv[i] = fr[96 + lane];
                const float* wr = sW + el * SWS;
                wAv[i] = wr[lane];
                wBv[i] = wr[32 + lane];
                wCv[i] = wr[64 + lane];
                wDv[i] = wr[96 + lane];
            }
#pragma unroll
            for (int i = 0; i < 4; i++) {
                int el = lbase + g * 4 + i;
                int dst = sDST[el];
                float ea0 = eav[i].x, e1x = eav[i].y, e1y = eav[i].z, e1z = eav[i].w;

                float mA = wAv[i] * g0v[i] * ea0;
                float dg = g1xv[i] * e1x + g1yv[i] * e1y + g1zv[i] * e1z;
                float mD = wDv[i] * dg * INV_SQRT3;
                float gb = wBv[i] * g0v[i];
                float mBx = gb * e1x, mBy = gb * e1y, mBz = gb * e1z;
                float wCe = wCv[i] * ea0;
                float mCx = wCe * g1xv[i], mCy = wCe * g1yv[i], mCz = wCe * g1zv[i];

                if (dst != run_dst) {
                    if (run_dst >= 0) {
                        float* nb = (float*)(n_buf4 + (size_t)run_dst * 64);
                        red_v4(nb + lane * 4,       acc0, acc1, acc2, acc3);
                        red_v4(nb + 128 + lane * 4, acc4, acc5, acc6, acc7);
                    }
                    run_dst = dst;
                    acc0 = mA;  acc1 = mD;  acc2 = mBx; acc3 = mCx;
                    acc4 = mBy; acc5 = mCy; acc6 = mBz; acc7 = mCz;
                } else {
                    acc0 += mA;  acc1 += mD;  acc2 += mBx; acc3 += mCx;
                    acc4 += mBy; acc5 += mCy; acc6 += mBz; acc7 += mCz;
                }

                // combined edge-output reductions (4 instead of 6)
                float mBdot = gb * (e1x * e1x + e1y * e1y + e1z * e1z);
                float mCdot = wCe * dg;
                float v0 = (mA * a0lo + mD * a0hi) * ea0
                         + (mBdot * b0lo + mCdot * b0hi) * INV_SQRT3;
                float vC = mA * a1lo + mD * a1hi;
                float v1x = vC * e1x + (mBx * b1lo + mCx * b1hi) * ea0;
                float v1y = vC * e1y + (mBy * b1lo + mCy * b1hi) * ea0;
                float v1z = vC * e1z + (mBz * b1lo + mCz * b1hi) * ea0;

#pragma unroll
                for (int off = 16; off > 0; off >>= 1) {
                    v0  += __shfl_xor_sync(FULL, v0,  off);
                    v1x += __shfl_xor_sync(FULL, v1x, off);
                    v1y += __shfl_xor_sync(FULL, v1y, off);
                    v1z += __shfl_xor_sync(FULL, v1z, off);
                }

                if (lane == 0) {
                    int eid = sEID[el];
                    float4 o;
                    o.x = ea0 + v0  * sosc;
                    o.y = e1x + v1x * sosc;
                    o.z = e1y + v1y * sosc;
                    o.w = e1z + v1z * sosc;
                    ((float4*)out_edge)[eid] = o;
                }
            }
        }
    } else {
        for (int le = 0; le < nloc; le++) {
            int el = lbase + le;
            int src = sSRC[el];
            int dst = sDST[el];
            float4 ea = sEA[el];
            float ea0 = ea.x, e1x = ea.y, e1y = ea.z, e1z = ea.w;

            const float* wr = sW + el * SWS;
            float wAs = wr[lane];
            float wBs = wr[32 + lane];
            float wCs = wr[64 + lane];
            float wDs = wr[96 + lane];

            const float* fr = f_buf + (size_t)src * 128;
            float g0  = fr[lane];
            float g1x = fr[32 + lane];
            float g1y = fr[64 + lane];
            float g1z = fr[96 + lane];

            float mA = wAs * g0 * ea0;
            float dg = g1x * e1x + g1y * e1y + g1z * e1z;
            float mD = wDs * dg * INV_SQRT3;
            float gb = wBs * g0;
            float mBx = gb * e1x, mBy = gb * e1y, mBz = gb * e1z;
            float wCe = wCs * ea0;
            float mCx = wCe * g1x, mCy = wCe * g1y, mCz = wCe * g1z;

            if (dst != run_dst) {
                if (run_dst >= 0) {
                    float* nb = (float*)(n_buf4 + (size_t)run_dst * 64);
                    red_v4(nb + lane * 4,       acc0, acc1, acc2, acc3);
                    red_v4(nb + 128 + lane * 4, acc4, acc5, acc6, acc7);
                }
                run_dst = dst;
                acc0 = mA;  acc1 = mD;  acc2 = mBx; acc3 = mCx;
                acc4 = mBy; acc5 = mCy; acc6 = mBz; acc7 = mCz;
            } else {
                acc0 += mA;  acc1 += mD;  acc2 += mBx; acc3 += mCx;
                acc4 += mBy; acc5 += mCy; acc6 += mBz; acc7 += mCz;
            }

            float mBdot = gb * (e1x * e1x + e1y * e1y + e1z * e1z);
            float mCdot = wCe * dg;
            float v0 = (mA * a0lo + mD * a0hi) * ea0
                     + (mBdot * b0lo + mCdot * b0hi) * INV_SQRT3;
            float vC = mA * a1lo + mD * a1hi;
            float v1x = vC * e1x + (mBx * b1lo + mCx * b1hi) * ea0;
            float v1y = vC * e1y + (mBy * b1lo + mCy * b1hi) * ea0;
            float v1z = vC * e1z + (mBz * b1lo + mCz * b1hi) * ea0;

#pragma unroll
            for (int off = 16; off > 0; off >>= 1) {
                v0  += __shfl_xor_sync(FULL, v0,  off);
                v1x += __shfl_xor_sync(FULL, v1x, off);
                v1y += __shfl_xor_sync(FULL, v1y, off);
                v1z += __shfl_xor_sync(FULL, v1z, off);
            }

            if (lane == 0) {
                int eid = sEID[el];
                float4 o;
                o.x = ea0 + v0  * sosc;
                o.y = e1x + v1x * sosc;
                o.z = e1y + v1y * sosc;
                o.w = e1z + v1z * sosc;
                ((float4*)out_edge)[eid] = o;
            }
        }
    }

    // final flush
    if (run_dst >= 0) {
        float* nb = (float*)(n_buf4 + (size_t)run_dst * 64);
        red_v4(nb + lane * 4,       acc0, acc1, acc2, acc3);
        red_v4(nb + 128 + lane * 4, acc4, acc5, acc6, acc7);
    }
}

// ---------------------------------------------------------------------------
// Kernel 3: node post-pass. One warp per 2 nodes; n broadcast via smem v4.
// ---------------------------------------------------------------------------
__global__ __launch_bounds__(256) void node_post_kernel(
    const float* __restrict__ node_attr,
    const float* __restrict__ w20,
    const float* __restrict__ w21,
    const float* __restrict__ w_alpha,
    float* __restrict__ out_node,
    int N)
{
    __shared__ float s20[2048], s21[2048], sal[64];
    __shared__ float4 sx[8][2][2][32];   // [wid][node][half][u]
    for (int i = threadIdx.x; i < 2048; i += blockDim.x) { s20[i] = w20[i]; s21[i] = w21[i]; }
    for (int i = threadIdx.x; i < 64; i += blockDim.x) sal[i] = w_alpha[i];
    __syncthreads();

    int warp = (blockIdx.x * blockDim.x + threadIdx.x) >> 5;
    int wid  = (threadIdx.x >> 5);
    int lane = threadIdx.x & 31;
    int nA = warp * 2;
    int nB = nA + 1;
    if (nA >= N) return;
    bool hasB = (nB < N);

    {
        float4 vA1 = n_buf4[(size_t)nA * 64 + lane];        // (mA,mD,mBx,mCx) sums
        float4 vA2 = n_buf4[(size_t)nA * 64 + 32 + lane];   // (mBy,mCy,mBz,mCz) sums
        sx[wid][0][0][lane] = make_float4(vA1.x, vA1.z, vA2.x, vA2.z); // n0a,n1ax,n1ay,n1az
        sx[wid][0][1][lane] = make_float4(vA1.y, vA1.w, vA2.y, vA2.w); // n0b,n1bx,n1by,n1bz
        if (hasB) {
            float4 vB1 = n_buf4[(size_t)nB * 64 + lane];
            float4 vB2 = n_buf4[(size_t)nB * 64 + 32 + lane];
            sx[wid][1][0][lane] = make_float4(vB1.x, vB1.z, vB2.x, vB2.z);
            sx[wid][1][1][lane] = make_float4(vB1.y, vB1.w, vB2.y, vB2.w);
        }
    }
    __syncwarp();

    float Ao0 = 0.f, Ao1x = 0.f, Ao1y = 0.f, Ao1z = 0.f, Aal = 0.f;
    float Bo0 = 0.f, Bo1x = 0.f, Bo1y = 0.f, Bo1z = 0.f, Bal = 0.f;

#pragma unroll
    for (int u = 0; u < 32; u++) {
        float wa = s20[u * 32 + lane];
        float wb = s21[u * 32 + lane];
        float wal = sal[u];

        float4 xa = sx[wid][0][0][u];
        Ao0 += xa.x * wa; Ao1x += xa.y * wb; Ao1y += xa.z * wb; Ao1z += xa.w * wb; Aal += xa.x * wal;
        float4 xb = sx[wid][1][0][u];
        Bo0 += xb.x * wa; Bo1x += xb.y * wb; Bo1y += xb.z * wb; Bo1z += xb.w * wb; Bal += xb.x * wal;
    }
#pragma unroll
    for (int u = 0; u < 32; u++) {
        float wa = s20[(u + 32) * 32 + lane];
        float wb = s21[(u + 32) * 32 + lane];
        float wal = sal[u + 32];

        float4 xa = sx[wid][0][1][u];
        Ao0 += xa.x * wa; Ao1x += xa.y * wb; Ao1y += xa.z * wb; Ao1z += xa.w * wb; Aal += xa.x * wal;
        float4 xb = sx[wid][1][1][u];
        Bo0 += xb.x * wa; Bo1x += xb.y * wb; Bo1y += xb.z * wb; Bo1z += xb.w * wb; Bal += xb.x * wal;
    }
    __syncwarp();

    const float s_mid  = 0.125f;                 // 1/sqrt(64)
    const float inv_nn = 0.35355339059327373f;   // 1/sqrt(8)
    float* st = (float*)&sx[wid][0][0][0];
    {
        float sc = node_attr[nA] * s_mid * inv_nn;   // one inv_nn per n-factor
        float k = (Aal * sc) * sc;                   // alpha * scale
        st[lane]          = k * Ao0;
        st[32 + 3 * lane] = k * Ao1x;
        st[33 + 3 * lane] = k * Ao1y;
        st[34 + 3 * lane] = k * Ao1z;
        __syncwarp();
        float4* on4 = (float4*)(out_node + (size_t)nA * 128);
        float4 cur = on4[lane];
        float4 add = ((const float4*)st)[lane];
        cur.x += add.x; cur.y += add.y; cur.z += add.z; cur.w += add.w;
        on4[lane] = cur;
        __syncwarp();
    }
    if (hasB) {
        float sc = node_attr[nB] * s_mid * inv_nn;
        float k = (Bal * sc) * sc;
        st[lane]          = k * Bo0;
        st[32 + 3 * lane] = k * Bo1x;
        st[33 + 3 * lane] = k * Bo1y;
        st[34 + 3 * lane] = k * Bo1z;
        __syncwarp();
        float4* on4 = (float4*)(out_node + (size_t)nB * 128);
        float4 cur = on4[lane];
        float4 add = ((const float4*)st)[lane];
        cur.x += add.x; cur.y += add.y; cur.z += add.z; cur.w += add.w;
        on4[lane] = cur;
    }
}

// ---------------------------------------------------------------------------
extern "C" void kernel_launch(void* const* d_in, const int* in_sizes, int n_in,
                              void* d_out, int out_size)
{
    const float* node_input   = (const float*)d_in[0];
    const float* node_attr    = (const float*)d_in[1];
    const int*   edge_src     = (const int*)  d_in[2];
    const int*   edge_dst     = (const int*)  d_in[3];
    const float* edge_attr    = (const float*)d_in[4];
    const float* edge_scalars = (const float*)d_in[5];
    const float* w_sc0        = (const float*)d_in[6];
    const float* w_sc1        = (const float*)d_in[7];
    const float* w_lin1_0     = (const float*)d_in[8];
    const float* w_lin1_1     = (const float*)d_in[9];
    const float* fc_w1        = (const float*)d_in[10];
    const float* fc_w2        = (const float*)d_in[11];
    const float* w_lin2_0     = (const float*)d_in[12];
    const float* w_lin2_1     = (const float*)d_in[13];
    const float* w_alpha      = (const float*)d_in[14];
    const float* w_se0a       = (const float*)d_in[15];
    const float* w_se0b       = (const float*)d_in[16];
    const float* w_se1a       = (const float*)d_in[17];
    const float* w_se1b       = (const float*)d_in[18];

    int N = in_sizes[0] / 128;
    int E = in_sizes[2];

    float* out_node = (float*)d_out;
    float* out_edge = (float*)d_out + (size_t)N * 128;

    // zero accumulators via captured memset nodes
    void* nbuf_ptr = nullptr;
    cudaGetSymbolAddress(&nbuf_ptr, n_buf4);
    cudaMemsetAsync(nbuf_ptr, 0, (size_t)N * 64 * sizeof(float4));
    void* deg_ptr = nullptr;
    cudaGetSymbolAddress(&deg_ptr, deg_buf);
    cudaMemsetAsync(deg_ptr, 0, (size_t)N * sizeof(int));

    const int SMEM_EDGE = SMEM_FLOATS * 4; // 104960 bytes
    cudaFuncSetAttribute(edge_fused_kernel,
                         cudaFuncAttributeMaxDynamicSharedMemorySize, SMEM_EDGE);

    // CSR build
    hist_kernel<<<divup(E, 256), 256>>>(edge_dst, E);
    scan_kernel<<<1, 1024>>>(N);
    scatter_kernel<<<divup(E, 256), 256>>>(edge_dst, E);

    node_pre_kernel<<<divup(N, 16), 256>>>(node_input, node_attr,
                                           w_sc0, w_sc1, w_lin1_0, w_lin1_1,
                                           out_node, N);

    edge_fused_kernel<<<divup(E, 128), 256, SMEM_EDGE>>>(
        edge_src, edge_dst, edge_attr, edge_scalars,
        fc_w1, fc_w2, w_se0a, w_se0b, w_se1a, w_se1b,
        out_edge, E);

    node_post_kernel<<<divup(N, 16), 256>>>(node_attr, w_lin2_0, w_lin2_1, w_alpha,
                                            out_node, N);
}

// round 7
// speedup vs baseline: 1.1781x; 1.1781x over previous
#include <cuda_runtime.h>
#include <math.h>
#include <stdint.h>

#define FULL 0xffffffffu
#define MAXN 50000

// Scratch (device globals; no allocation allowed)
__device__ float  f_buf[MAXN * 128];      // per-node lin1 features [f0|f1x|f1y|f1z]
// per-node accum: [node][ lane*4 -> (mA,mD,mBx,mCx) | 128 + lane*4 -> (mBy,mCy,mBz,mCz) ]
__device__ float4 n_buf4[MAXN * 64];

__host__ __device__ __forceinline__ int divup(int a, int b) { return (a + b - 1) / b; }

static __device__ __forceinline__ void red_v4(float* p, float a, float b, float c, float d) {
    asm volatile("red.global.add.v4.f32 [%0], {%1,%2,%3,%4};"
                 :: "l"(p), "f"(a), "f"(b), "f"(c), "f"(d) : "memory");
}
static __device__ __forceinline__ unsigned long long pack2(float lo, float hi) {
    unsigned long long r;
    asm("mov.b64 %0, {%1,%2};" : "=l"(r) : "f"(lo), "f"(hi));
    return r;
}
static __device__ __forceinline__ void fma2(unsigned long long& acc, unsigned long long a, unsigned long long b) {
    asm("fma.rn.f32x2 %0, %1, %2, %0;" : "+l"(acc) : "l"(a), "l"(b));
}
static __device__ __forceinline__ float2 unpack2(unsigned long long v) {
    float2 r;
    asm("mov.b64 {%0,%1}, %2;" : "=f"(r.x), "=f"(r.y) : "l"(v));
    return r;
}
static __device__ __forceinline__ float pick(unsigned long long v, int sel) {
    float2 t = unpack2(v);
    return sel ? t.y : t.x;
}
static __device__ __forceinline__ uint32_t to_tf32(float f) {
    uint32_t r; asm("cvt.rna.tf32.f32 %0, %1;" : "=r"(r) : "f"(f)); return r;
}

// ---------------------------------------------------------------------------
// Kernel 1: node pre-pass. One warp per 4 nodes, f32x2-paired accumulation.
// ---------------------------------------------------------------------------
__global__ __launch_bounds__(256) void node_pre_kernel(
    const float* __restrict__ node_input,
    const float* __restrict__ node_attr,
    const float* __restrict__ w_sc0,
    const float* __restrict__ w_sc1,
    const float* __restrict__ w_l0,
    const float* __restrict__ w_l1,
    float* __restrict__ out_node,
    int N)
{
    __shared__ float s0[1024], s1[1024], s2[1024], s3[1024];
    __shared__ float4 stg[8][32][4];   // [warp][u][comp]: comp f4 = value for nodes 0..3
    for (int i = threadIdx.x; i < 1024; i += blockDim.x) {
        s0[i] = w_sc0[i]; s1[i] = w_sc1[i]; s2[i] = w_l0[i]; s3[i] = w_l1[i];
    }
    __syncthreads();

    int warp = (blockIdx.x * blockDim.x + threadIdx.x) >> 5;
    int wid  = (threadIdx.x >> 5);
    int lane = threadIdx.x & 31;
    int base = warp * 4;
    if (base >= N) return;

    // stage 4 node rows: comp-major pairs for f32x2
    {
        float x0[4], xa[4], xb[4], xc[4];
#pragma unroll
        for (int j = 0; j < 4; j++) {
            int n = min(base + j, N - 1);
            const float* row = node_input + (size_t)n * 128;
            x0[j] = row[lane];
            xa[j] = row[32 + 3 * lane];
            xb[j] = row[33 + 3 * lane];
            xc[j] = row[34 + 3 * lane];
        }
        stg[wid][lane][0] = make_float4(x0[0], x0[1], x0[2], x0[3]);
        stg[wid][lane][1] = make_float4(xa[0], xa[1], xa[2], xa[3]);
        stg[wid][lane][2] = make_float4(xb[0], xb[1], xb[2], xb[3]);
        stg[wid][lane][3] = make_float4(xc[0], xc[1], xc[2], xc[3]);
    }
    __syncwarp();

    // accumulators: [quantity][pair]; quantities: sc0,f0,sc1x,sc1y,sc1z,f1x,f1y,f1z
    unsigned long long acc[8][2];
#pragma unroll
    for (int i = 0; i < 8; i++) { acc[i][0] = 0ull; acc[i][1] = 0ull; }

#pragma unroll
    for (int u = 0; u < 32; u++) {
        float w0 = s0[u * 32 + lane];
        float w1 = s1[u * 32 + lane];
        float w2 = s2[u * 32 + lane];
        float w3 = s3[u * 32 + lane];
        unsigned long long ww0 = pack2(w0, w0);
        unsigned long long ww1 = pack2(w1, w1);
        unsigned long long ww2 = pack2(w2, w2);
        unsigned long long ww3 = pack2(w3, w3);

        float4 q0 = stg[wid][u][0];
        float4 q1 = stg[wid][u][1];
        float4 q2 = stg[wid][u][2];
        float4 q3 = stg[wid][u][3];
        unsigned long long q0a = pack2(q0.x, q0.y), q0b = pack2(q0.z, q0.w);
        unsigned long long q1a = pack2(q1.x, q1.y), q1b = pack2(q1.z, q1.w);
        unsigned long long q2a = pack2(q2.x, q2.y), q2b = pack2(q2.z, q2.w);
        unsigned long long q3a = pack2(q3.x, q3.y), q3b = pack2(q3.z, q3.w);

        fma2(acc[0][0], q0a, ww0); fma2(acc[0][1], q0b, ww0);   // sc0
        fma2(acc[1][0], q0a, ww2); fma2(acc[1][1], q0b, ww2);   // f0
        fma2(acc[2][0], q1a, ww1); fma2(acc[2][1], q1b, ww1);   // sc1x
        fma2(acc[3][0], q2a, ww1); fma2(acc[3][1], q2b, ww1);   // sc1y
        fma2(acc[4][0], q3a, ww1); fma2(acc[4][1], q3b, ww1);   // sc1z
        fma2(acc[5][0], q1a, ww3); fma2(acc[5][1], q1b, ww3);   // f1x
        fma2(acc[6][0], q2a, ww3); fma2(acc[6][1], q2b, ww3);   // f1y
        fma2(acc[7][0], q3a, ww3); fma2(acc[7][1], q3b, ww3);   // f1z
    }
    __syncwarp();

    const float s_in = 0.17677669529663687f; // 1/sqrt(32)
    float* st = (float*)&stg[wid][0][0];

#pragma unroll
    for (int j = 0; j < 4; j++) {
        int n = base + j;
        if (n >= N) break;
        int h = j >> 1, sel = j & 1;
        float sA = node_attr[n] * s_in;

        float sc0  = pick(acc[0][h], sel) * sA;
        float f0   = pick(acc[1][h], sel) * sA;
        float sc1x = pick(acc[2][h], sel) * sA;
        float sc1y = pick(acc[3][h], sel) * sA;
        float sc1z = pick(acc[4][h], sel) * sA;
        float f1x  = pick(acc[5][h], sel) * sA;
        float f1y  = pick(acc[6][h], sel) * sA;
        float f1z  = pick(acc[7][h], sel) * sA;

        st[lane]          = sc0;
        st[32 + 3 * lane] = sc1x;
        st[33 + 3 * lane] = sc1y;
        st[34 + 3 * lane] = sc1z;
        __syncwarp();
        ((float4*)(out_node + (size_t)n * 128))[lane] = ((const float4*)st)[lane];
        __syncwarp();

        float* fb = f_buf + (size_t)n * 128;
        fb[lane]      = f0;
        fb[32 + lane] = f1x;
        fb[64 + lane] = f1y;
        fb[96 + lane] = f1z;
    }
}

// ---------------------------------------------------------------------------
// Kernel 2 (fused): per block of 128 edges:
//   GEMM1: H = sin(ES@W1*0.25) (f32x2), GEMM2: W = H@W2*0.125 (tf32 mma),
//   batched message phase, vector atomics, merged 4-way edge reductions.
// ---------------------------------------------------------------------------
#define EPAD 132
#define HP   68
#define SWS  134

__global__ void __launch_bounds__(256, 2) edge_fused_kernel(
    const int*   __restrict__ edge_src,
    const int*   __restrict__ edge_dst,
    const float* __restrict__ edge_attr,
    const float* __restrict__ edge_scalars,
    const float* __restrict__ fc_w1,
    const float* __restrict__ fc_w2,
    const float* __restrict__ w_se0a,
    const float* __restrict__ w_se0b,
    const float* __restrict__ w_se1a,
    const float* __restrict__ w_se1b,
    float* __restrict__ out_edge,
    int E)
{
    extern __shared__ float sm[];
    float* sBf    = sm;                  // 8192: B fragments (tf32 bits)
    float* region = sm + 8192;
    float* sW1  = region;                // 1024
    float* sEST = region + 1024;         // 16*132 = 2112 (k-major ES^T)
    float* sH   = region + 3136;         // 128*68 = 8704 (edge-major, tf32 bits)
    float* sW   = region;                // phase B: 128*134 = 17152

    int t = threadIdx.x;
    int e0 = blockIdx.x * 128;
    int lane = t & 31;
    int wwid = t >> 5;

    // ---- stage W1 (scaled), ES tile, and B fragments (tf32, scaled) ----
    {
        float4 v = ((const float4*)fc_w1)[t];
        v.x *= 0.25f; v.y *= 0.25f; v.z *= 0.25f; v.w *= 0.25f;
        ((float4*)sW1)[t] = v;
    }
#pragma unroll
    for (int r = 0; r < 2; r++) {
        int fidx = t + r * 256;     // 0..511 float4s of the ES tile
        int e = fidx >> 2;          // 0..127
        int k4 = fidx & 3;
        float4 v = make_float4(0.f, 0.f, 0.f, 0.f);
        if (e0 + e < E) v = ((const float4*)edge_scalars)[(size_t)(e0 + e) * 4 + k4];
        sEST[(k4 * 4 + 0) * EPAD + e] = v.x;
        sEST[(k4 * 4 + 1) * EPAD + e] = v.y;
        sEST[(k4 * 4 + 2) * EPAD + e] = v.z;
        sEST[(k4 * 4 + 3) * EPAD + e] = v.w;
    }
    {
        uint32_t* sBfu = (uint32_t*)sBf;
#pragma unroll
        for (int rep = 0; rep < 32; rep++) {
            int idx = rep * 256 + t;        // 0..8191, coalesced gmem reads
            int n = idx & 127;
            int k = idx >> 7;
            float val = fc_w2[k * 128 + n] * 0.125f;
            int nt = n >> 3, ks = k >> 3, rb = (k >> 2) & 1;
            int ln = ((n & 7) << 2) | (k & 3);
            sBfu[(nt * 8 + ks) * 64 + ln * 2 + rb] = to_tf32(val);
        }
    }
    __syncthreads();

    // ---- GEMM1: thread tile = 4 edges (2 pairs, 64 apart) x 8 cols ----
    {
        int txe = t & 31;   // edge pairs at txe*2 and txe*2+64
        int tyc = t >> 5;   // cols tyc*8 + j
        unsigned long long acc[8][2];
#pragma unroll
        for (int j = 0; j < 8; j++) { acc[j][0] = 0ull; acc[j][1] = 0ull; }
#pragma unroll
        for (int k = 0; k < 16; k++) {
            unsigned long long a0 = *(const unsigned long long*)(sEST + k * EPAD + txe * 2);
            unsigned long long a1 = *(const unsigned long long*)(sEST + k * EPAD + txe * 2 + 64);
#pragma unroll
            for (int j = 0; j < 8; j++) {
                float b = sW1[k * 64 + tyc * 8 + j];
                unsigned long long bb = pack2(b, b);
                fma2(acc[j][0], a0, bb);
                fma2(acc[j][1], a1, bb);
            }
        }
        uint32_t* sHu = (uint32_t*)sH;
#pragma unroll
        for (int j = 0; j < 8; j++) {
            int col = tyc * 8 + j;
#pragma unroll
            for (int i = 0; i < 2; i++) {
                float2 v = unpack2(acc[j][i]);
                int e = txe * 2 + 64 * i;
                sHu[e * HP + col]       = to_tf32(__sinf(v.x));
                sHu[(e + 1) * HP + col] = to_tf32(__sinf(v.y));
            }
        }
    }
    __syncthreads();

    // ---- load A fragments (16 edges per warp, K=64 -> 8 ksteps) ----
    uint32_t afr[8][4];
    {
        const uint32_t* sHu = (const uint32_t*)sH;
        int er = wwid * 16 + (lane >> 2);
        int kl = lane & 3;
#pragma unroll
        for (int ks = 0; ks < 8; ks++) {
            int k0 = ks * 8 + kl;
            afr[ks][0] = sHu[er * HP + k0];
            afr[ks][1] = sHu[(er + 8) * HP + k0];
            afr[ks][2] = sHu[er * HP + k0 + 4];
            afr[ks][3] = sHu[(er + 8) * HP + k0 + 4];
        }
    }
    __syncthreads();   // sH dead; region becomes sW

    // ---- GEMM2: tf32 mma, warp computes 16 edges x 128 outs ----
    {
        const uint32_t* bf = (const uint32_t*)sBf;
        int er = wwid * 16 + (lane >> 2);
        int nb = (lane & 3) * 2;
#pragma unroll
        for (int nt = 0; nt < 16; nt++) {
            float c0 = 0.f, c1 = 0.f, c2 = 0.f, c3 = 0.f;
#pragma unroll
            for (int ks = 0; ks < 8; ks++) {
                uint2 b = *(const uint2*)(bf + (nt * 8 + ks) * 64 + lane * 2);
                asm volatile(
                    "mma.sync.aligned.m16n8k8.row.col.f32.tf32.tf32.f32 "
                    "{%0,%1,%2,%3},{%4,%5,%6,%7},{%8,%9},{%0,%1,%2,%3};"
                    : "+f"(c0), "+f"(c1), "+f"(c2), "+f"(c3)
                    : "r"(afr[ks][0]), "r"(afr[ks][1]), "r"(afr[ks][2]), "r"(afr[ks][3]),
                      "r"(b.x), "r"(b.y));
            }
            int n = nt * 8 + nb;
            *(float2*)(sW + er * SWS + n)       = make_float2(c0, c1);
            *(float2*)(sW + (er + 8) * SWS + n) = make_float2(c2, c3);
        }
    }
    __syncthreads();

    // ---- message phase: warp handles edges [base, base+16), batched by 4 ----
    float a0lo = w_se0a[lane],      a0hi = w_se0a[32 + lane];
    float b0lo = w_se0b[lane],      b0hi = w_se0b[32 + lane];
    float a1lo = w_se1a[lane],      a1hi = w_se1a[32 + lane];
    float b1lo = w_se1b[lane],      b1hi = w_se1b[32 + lane];

    const float INV_SQRT3 = 0.5773502691896258f;
    const float s_se   = 0.08838834764831845f;   // 1/sqrt(128)
    const float inv_nn = 0.35355339059327373f;   // 1/sqrt(8)
    const float sosc   = s_se * inv_nn;

    int base = e0 + wwid * 16;

    if (base + 16 <= E) {
        // fast path, no bounds checks
#pragma unroll 1
        for (int g = 0; g < 4; g++) {
            int   dstv[4];
            float4 eav[4];
            float g0v[4], g1xv[4], g1yv[4], g1zv[4];
            float wAv[4], wBv[4], wCv[4], wDv[4];
#pragma unroll
            for (int i = 0; i < 4; i++) {
                int eg = base + g * 4 + i;
                int el = wwid * 16 + g * 4 + i;
                int src = edge_src[eg];
                dstv[i] = edge_dst[eg];
                eav[i] = ((const float4*)edge_attr)[eg];
                const float* fr = f_buf + (size_t)src * 128;
                g0v[i]  = fr[lane];
                g1xv[i] = fr[32 + lane];
                g1yv[i] = fr[64 + lane];
                g1zv[i] = fr[96 + lane];
                const float* wr = sW + el * SWS;
                wAv[i] = wr[lane];
                wBv[i] = wr[32 + lane];
                wCv[i] = wr[64 + lane];
                wDv[i] = wr[96 + lane];
            }
#pragma unroll
            for (int i = 0; i < 4; i++) {
                float ea0 = eav[i].x, e1x = eav[i].y, e1y = eav[i].z, e1z = eav[i].w;

                float mA = wAv[i] * g0v[i] * ea0;
                float dg = g1xv[i] * e1x + g1yv[i] * e1y + g1zv[i] * e1z;
                float mD = wDv[i] * dg * INV_SQRT3;
                float gb = wBv[i] * g0v[i];
                float mBx = gb * e1x, mBy = gb * e1y, mBz = gb * e1z;
                float wCe = wCv[i] * ea0;
                float mCx = wCe * g1xv[i], mCy = wCe * g1yv[i], mCz = wCe * g1zv[i];

                float* nb = (float*)(n_buf4 + (size_t)dstv[i] * 64);
                red_v4(nb + lane * 4,       mA,  mD,  mBx, mCx);
                red_v4(nb + 128 + lane * 4, mBy, mCy, mBz, mCz);

                // merged edge-output reductions (4 instead of 6)
                float mBdot = gb * (e1x * e1x + e1y * e1y + e1z * e1z);
                float mCdot = wCe * dg;
                float v0 = (mA * a0lo + mD * a0hi) * ea0
                         + (mBdot * b0lo + mCdot * b0hi) * INV_SQRT3;
                float vC = mA * a1lo + mD * a1hi;
                float v1x = vC * e1x + (mBx * b1lo + mCx * b1hi) * ea0;
                float v1y = vC * e1y + (mBy * b1lo + mCy * b1hi) * ea0;
                float v1z = vC * e1z + (mBz * b1lo + mCz * b1hi) * ea0;

#pragma unroll
                for (int off = 16; off > 0; off >>= 1) {
                    v0  += __shfl_xor_sync(FULL, v0,  off);
                    v1x += __shfl_xor_sync(FULL, v1x, off);
                    v1y += __shfl_xor_sync(FULL, v1y, off);
                    v1z += __shfl_xor_sync(FULL, v1z, off);
                }

                if (lane == 0) {
                    float4 o;
                    o.x = ea0 + v0  * sosc;
                    o.y = e1x + v1x * sosc;
                    o.z = e1y + v1y * sosc;
                    o.w = e1z + v1z * sosc;
                    ((float4*)out_edge)[base + g * 4 + i] = o;
                }
            }
        }
    } else {
        // guarded tail path
        for (int le = 0; le < 16; le++) {
            int eg = base + le;
            if (eg >= E) break;
            int el = wwid * 16 + le;

            int src = edge_src[eg];
            int dst = edge_dst[eg];
            float4 ea = ((const float4*)edge_attr)[eg];
            float ea0 = ea.x, e1x = ea.y, e1y = ea.z, e1z = ea.w;

            const float* wr = sW + el * SWS;
            float wAs = wr[lane];
            float wBs = wr[32 + lane];
            float wCs = wr[64 + lane];
            float wDs = wr[96 + lane];

            const float* fr = f_buf + (size_t)src * 128;
            float g0  = fr[lane];
            float g1x = fr[32 + lane];
            float g1y = fr[64 + lane];
            float g1z = fr[96 + lane];

            float mA = wAs * g0 * ea0;
            float dg = g1x * e1x + g1y * e1y + g1z * e1z;
            float mD = wDs * dg * INV_SQRT3;
            float gb = wBs * g0;
            float mBx = gb * e1x, mBy = gb * e1y, mBz = gb * e1z;
            float wCe = wCs * ea0;
            float mCx = wCe * g1x, mCy = wCe * g1y, mCz = wCe * g1z;

            float* nb = (float*)(n_buf4 + (size_t)dst * 64);
            red_v4(nb + lane * 4,       mA,  mD,  mBx, mCx);
            red_v4(nb + 128 + lane * 4, mBy, mCy, mBz, mCz);

            float mBdot = gb * (e1x * e1x + e1y * e1y + e1z * e1z);
            float mCdot = wCe * dg;
            float v0 = (mA * a0lo + mD * a0hi) * ea0
                     + (mBdot * b0lo + mCdot * b0hi) * INV_SQRT3;
            float vC = mA * a1lo + mD * a1hi;
            float v1x = vC * e1x + (mBx * b1lo + mCx * b1hi) * ea0;
            float v1y = vC * e1y + (mBy * b1lo + mCy * b1hi) * ea0;
            float v1z = vC * e1z + (mBz * b1lo + mCz * b1hi) * ea0;

#pragma unroll
            for (int off = 16; off > 0; off >>= 1) {
                v0  += __shfl_xor_sync(FULL, v0,  off);
                v1x += __shfl_xor_sync(FULL, v1x, off);
                v1y += __shfl_xor_sync(FULL, v1y, off);
                v1z += __shfl_xor_sync(FULL, v1z, off);
            }

            if (lane == 0) {
                float4 o;
                o.x = ea0 + v0  * sosc;
                o.y = e1x + v1x * sosc;
                o.z = e1y + v1y * sosc;
                o.w = e1z + v1z * sosc;
                ((float4*)out_edge)[eg] = o;
            }
        }
    }
}

// ---------------------------------------------------------------------------
// Kernel 3: node post-pass. One warp per 4 nodes, f32x2-paired accumulation.
// Dynamic smem: s20(2048) s21(2048) sal(64) stg(8192 floats) = 49408 bytes.
// ---------------------------------------------------------------------------
__global__ __launch_bounds__(256) void node_post_kernel(
    const float* __restrict__ node_attr,
    const float* __restrict__ w20,
    const float* __restrict__ w21,
    const float* __restrict__ w_alpha,
    float* __restrict__ out_node,
    int N)
{
    extern __shared__ float smp[];
    float*  s20 = smp;            // 2048
    float*  s21 = smp + 2048;     // 2048
    float*  sal = smp + 4096;     // 64
    float4* stg = (float4*)(smp + 4160);  // [wid][u][half][comp] = ((wid*32+u)*2+h)*4+c

    for (int i = threadIdx.x; i < 2048; i += blockDim.x) { s20[i] = w20[i]; s21[i] = w21[i]; }
    for (int i = threadIdx.x; i < 64; i += blockDim.x) sal[i] = w_alpha[i];
    __syncthreads();

    int warp = (blockIdx.x * blockDim.x + threadIdx.x) >> 5;
    int wid  = (threadIdx.x >> 5);
    int lane = threadIdx.x & 31;
    int base = warp * 4;
    if (base >= N) return;

    float4* stgW = stg + (size_t)wid * 32 * 2 * 4;

    // stage: half0 comps (n0a, n1ax, n1ay, n1az), half1 (n0b, n1bx, n1by, n1bz)
    {
        float4 v1[4], v2[4];
#pragma unroll
        for (int j = 0; j < 4; j++) {
            int n = min(base + j, N - 1);
            v1[j] = n_buf4[(size_t)n * 64 + lane];       // (mA,mD,mBx,mCx) sums
            v2[j] = n_buf4[(size_t)n * 64 + 32 + lane];  // (mBy,mCy,mBz,mCz) sums
        }
        float4* s = stgW + lane * 8;
        s[0] = make_float4(v1[0].x, v1[1].x, v1[2].x, v1[3].x); // n0a
        s[1] = make_float4(v1[0].z, v1[1].z, v1[2].z, v1[3].z); // n1ax
        s[2] = make_float4(v2[0].x, v2[1].x, v2[2].x, v2[3].x); // n1ay
        s[3] = make_float4(v2[0].z, v2[1].z, v2[2].z, v2[3].z); // n1az
        s[4] = make_float4(v1[0].y, v1[1].y, v1[2].y, v1[3].y); // n0b
        s[5] = make_float4(v1[0].w, v1[1].w, v1[2].w, v1[3].w); // n1bx
        s[6] = make_float4(v2[0].y, v2[1].y, v2[2].y, v2[3].y); // n1by
        s[7] = make_float4(v2[0].w, v2[1].w, v2[2].w, v2[3].w); // n1bz
    }
    __syncwarp();

    // accumulators: o0, o1x, o1y, o1z, al ; pairs (n0,n1),(n2,n3)
    unsigned long long acc[5][2];
#pragma unroll
    for (int i = 0; i < 5; i++) { acc[i][0] = 0ull; acc[i][1] = 0ull; }

#pragma unroll
    for (int u = 0; u < 32; u++) {
#pragma unroll
        for (int h = 0; h < 2; h++) {
            float wa  = s20[(u + h * 32) * 32 + lane];
            float wb  = s21[(u + h * 32) * 32 + lane];
            float wal = sal[u + h * 32];
            unsigned long long wap  = pack2(wa, wa);
            unsigned long long wbp  = pack2(wb, wb);
            unsigned long long walp = pack2(wal, wal);

            const float4* s = stgW + (u * 2 + h) * 4;
            float4 q0 = s[0];  // x0 (n0a or n0b)
            float4 qx = s[1];
            float4 qy = s[2];
            float4 qz = s[3];
            unsigned long long q0a = pack2(q0.x, q0.y), q0b = pack2(q0.z, q0.w);
            unsigned long long qxa = pack2(qx.x, qx.y), qxb = pack2(qx.z, qx.w);
            unsigned long long qya = pack2(qy.x, qy.y), qyb = pack2(qy.z, qy.w);
            unsigned long long qza = pack2(qz.x, qz.y), qzb = pack2(qz.z, qz.w);

            fma2(acc[0][0], q0a, wap);  fma2(acc[0][1], q0b, wap);   // o0
            fma2(acc[1][0], qxa, wbp);  fma2(acc[1][1], qxb, wbp);   // o1x
            fma2(acc[2][0], qya, wbp);  fma2(acc[2][1], qyb, wbp);   // o1y
            fma2(acc[3][0], qza, wbp);  fma2(acc[3][1], qzb, wbp);   // o1z
            fma2(acc[4][0], q0a, walp); fma2(acc[4][1], q0b, walp);  // alpha
        }
    }
    __syncwarp();

    const float s_mid  = 0.125f;                 // 1/sqrt(64)
    const float inv_nn = 0.35355339059327373f;   // 1/sqrt(8)
    float* st = (float*)stgW;

#pragma unroll
    for (int j = 0; j < 4; j++) {
        int n = base + j;
        if (n >= N) break;
        int h = j >> 1, sel = j & 1;

        float o0  = pick(acc[0][h], sel);
        float o1x = pick(acc[1][h], sel);
        float o1y = pick(acc[2][h], sel);
        float o1z = pick(acc[3][h], sel);
        float al  = pick(acc[4][h], sel);

        float sc = node_attr[n] * s_mid * inv_nn;
        float k = (al * sc) * sc;

        st[lane]          = k * o0;
        st[32 + 3 * lane] = k * o1x;
        st[33 + 3 * lane] = k * o1y;
        st[34 + 3 * lane] = k * o1z;
        __syncwarp();
        float4* on4 = (float4*)(out_node + (size_t)n * 128);
        float4 cur = on4[lane];
        float4 add = ((const float4*)st)[lane];
        cur.x += add.x; cur.y += add.y; cur.z += add.z; cur.w += add.w;
        on4[lane] = cur;
        __syncwarp();
    }
}

// ---------------------------------------------------------------------------
extern "C" void kernel_launch(void* const* d_in, const int* in_sizes, int n_in,
                              void* d_out, int out_size)
{
    const float* node_input   = (const float*)d_in[0];
    const float* node_attr    = (const float*)d_in[1];
    const int*   edge_src     = (const int*)  d_in[2];
    const int*   edge_dst     = (const int*)  d_in[3];
    const float* edge_attr    = (const float*)d_in[4];
    const float* edge_scalars = (const float*)d_in[5];
    const float* w_sc0        = (const float*)d_in[6];
    const float* w_sc1        = (const float*)d_in[7];
    const float* w_lin1_0     = (const float*)d_in[8];
    const float* w_lin1_1     = (const float*)d_in[9];
    const float* fc_w1        = (const float*)d_in[10];
    const float* fc_w2        = (const float*)d_in[11];
    const float* w_lin2_0     = (const float*)d_in[12];
    const float* w_lin2_1     = (const float*)d_in[13];
    const float* w_alpha      = (const float*)d_in[14];
    const float* w_se0a       = (const float*)d_in[15];
    const float* w_se0b       = (const float*)d_in[16];
    const float* w_se1a       = (const float*)d_in[17];
    const float* w_se1b       = (const float*)d_in[18];

    int N = in_sizes[0] / 128;
    int E = in_sizes[2];

    float* out_node = (float*)d_out;
    float* out_edge = (float*)d_out + (size_t)N * 128;

    // zero the accumulator via a captured memset node
    void* nbuf_ptr = nullptr;
    cudaGetSymbolAddress(&nbuf_ptr, n_buf4);
    cudaMemsetAsync(nbuf_ptr, 0, (size_t)N * 64 * sizeof(float4));

    const int SMEM_EDGE = (8192 + 17152) * 4; // 101376 bytes
    cudaFuncSetAttribute(edge_fused_kernel,
                         cudaFuncAttributeMaxDynamicSharedMemorySize, SMEM_EDGE);
    const int SMEM_POST = (4160 + 8192) * 4;  // 49408 bytes
    cudaFuncSetAttribute(node_post_kernel,
                         cudaFuncAttributeMaxDynamicSharedMemorySize, SMEM_POST);

    // 8 warps/block, 4 nodes per warp
    node_pre_kernel<<<divup(N, 32), 256>>>(node_input, node_attr,
                                           w_sc0, w_sc1, w_lin1_0, w_lin1_1,
                                           out_node, N);

    edge_fused_kernel<<<divup(E, 128), 256, SMEM_EDGE>>>(
        edge_src, edge_dst, edge_attr, edge_scalars,
        fc_w1, fc_w2, w_se0a, w_se0b, w_se1a, w_se1b,
        out_edge, E);

    node_post_kernel<<<divup(N, 32), 256, SMEM_POST>>>(node_attr, w_lin2_0, w_lin2_1, w_alpha,
                                                       out_node, N);
}

// round 8
// speedup vs baseline: 1.3001x; 1.1036x over previous
#include <cuda_runtime.h>
#include <math.h>
#include <stdint.h>

#define FULL 0xffffffffu
#define MAXN 50000

// Scratch (device globals; no allocation allowed)
__device__ float  f_buf[MAXN * 128];      // per-node lin1 features [f0|f1x|f1y|f1z]
// per-node accum: [node][ lane*4 -> (mA,mD,mBx,mCx) | 128 + lane*4 -> (mBy,mCy,mBz,mCz) ]
__device__ float4 n_buf4[MAXN * 64];
__device__ uint32_t bfrag_global[8192];   // pre-converted tf32 B fragments of fc_w2*0.125

__host__ __device__ __forceinline__ int divup(int a, int b) { return (a + b - 1) / b; }

static __device__ __forceinline__ void red_v4(float* p, float a, float b, float c, float d) {
    asm volatile("red.global.add.v4.f32 [%0], {%1,%2,%3,%4};"
                 :: "l"(p), "f"(a), "f"(b), "f"(c), "f"(d) : "memory");
}
static __device__ __forceinline__ unsigned long long pack2(float lo, float hi) {
    unsigned long long r;
    asm("mov.b64 %0, {%1,%2};" : "=l"(r) : "f"(lo), "f"(hi));
    return r;
}
static __device__ __forceinline__ void fma2(unsigned long long& acc, unsigned long long a, unsigned long long b) {
    asm("fma.rn.f32x2 %0, %1, %2, %0;" : "+l"(acc) : "l"(a), "l"(b));
}
static __device__ __forceinline__ float2 unpack2(unsigned long long v) {
    float2 r;
    asm("mov.b64 {%0,%1}, %2;" : "=f"(r.x), "=f"(r.y) : "l"(v));
    return r;
}
static __device__ __forceinline__ float pick(unsigned long long v, int sel) {
    float2 t = unpack2(v);
    return sel ? t.y : t.x;
}
static __device__ __forceinline__ uint32_t to_tf32(float f) {
    uint32_t r; asm("cvt.rna.tf32.f32 %0, %1;" : "=r"(r) : "f"(f)); return r;
}

// ---------------------------------------------------------------------------
// One-off: convert fc_w2*0.125 into tf32 mma B-fragment layout.
// ---------------------------------------------------------------------------
__global__ __launch_bounds__(256) void prep_bfrag_kernel(const float* __restrict__ fc_w2) {
    int idx = blockIdx.x * 256 + threadIdx.x;   // 0..8191
    int n = idx & 127;
    int k = idx >> 7;
    float val = fc_w2[k * 128 + n] * 0.125f;
    int nt = n >> 3, ks = k >> 3, rb = (k >> 2) & 1;
    int ln = ((n & 7) << 2) | (k & 3);
    bfrag_global[(nt * 8 + ks) * 64 + ln * 2 + rb] = to_tf32(val);
}

// ---------------------------------------------------------------------------
// Kernel 1: node pre-pass. One warp per 4 nodes, f32x2-paired accumulation.
// ---------------------------------------------------------------------------
__global__ __launch_bounds__(256) void node_pre_kernel(
    const float* __restrict__ node_input,
    const float* __restrict__ node_attr,
    const float* __restrict__ w_sc0,
    const float* __restrict__ w_sc1,
    const float* __restrict__ w_l0,
    const float* __restrict__ w_l1,
    float* __restrict__ out_node,
    int N)
{
    __shared__ float s0[1024], s1[1024], s2[1024], s3[1024];
    __shared__ float4 stg[8][32][4];   // [warp][u][comp]: comp f4 = value for nodes 0..3
    for (int i = threadIdx.x; i < 1024; i += blockDim.x) {
        s0[i] = w_sc0[i]; s1[i] = w_sc1[i]; s2[i] = w_l0[i]; s3[i] = w_l1[i];
    }
    __syncthreads();

    int warp = (blockIdx.x * blockDim.x + threadIdx.x) >> 5;
    int wid  = (threadIdx.x >> 5);
    int lane = threadIdx.x & 31;
    int base = warp * 4;
    if (base >= N) return;

    // stage 4 node rows: comp-major pairs for f32x2
    {
        float x0[4], xa[4], xb[4], xc[4];
#pragma unroll
        for (int j = 0; j < 4; j++) {
            int n = min(base + j, N - 1);
            const float* row = node_input + (size_t)n * 128;
            x0[j] = row[lane];
            xa[j] = row[32 + 3 * lane];
            xb[j] = row[33 + 3 * lane];
            xc[j] = row[34 + 3 * lane];
        }
        stg[wid][lane][0] = make_float4(x0[0], x0[1], x0[2], x0[3]);
        stg[wid][lane][1] = make_float4(xa[0], xa[1], xa[2], xa[3]);
        stg[wid][lane][2] = make_float4(xb[0], xb[1], xb[2], xb[3]);
        stg[wid][lane][3] = make_float4(xc[0], xc[1], xc[2], xc[3]);
    }
    __syncwarp();

    // accumulators: [quantity][pair]; quantities: sc0,f0,sc1x,sc1y,sc1z,f1x,f1y,f1z
    unsigned long long acc[8][2];
#pragma unroll
    for (int i = 0; i < 8; i++) { acc[i][0] = 0ull; acc[i][1] = 0ull; }

#pragma unroll
    for (int u = 0; u < 32; u++) {
        float w0 = s0[u * 32 + lane];
        float w1 = s1[u * 32 + lane];
        float w2 = s2[u * 32 + lane];
        float w3 = s3[u * 32 + lane];
        unsigned long long ww0 = pack2(w0, w0);
        unsigned long long ww1 = pack2(w1, w1);
        unsigned long long ww2 = pack2(w2, w2);
        unsigned long long ww3 = pack2(w3, w3);

        float4 q0 = stg[wid][u][0];
        float4 q1 = stg[wid][u][1];
        float4 q2 = stg[wid][u][2];
        float4 q3 = stg[wid][u][3];
        unsigned long long q0a = pack2(q0.x, q0.y), q0b = pack2(q0.z, q0.w);
        unsigned long long q1a = pack2(q1.x, q1.y), q1b = pack2(q1.z, q1.w);
        unsigned long long q2a = pack2(q2.x, q2.y), q2b = pack2(q2.z, q2.w);
        unsigned long long q3a = pack2(q3.x, q3.y), q3b = pack2(q3.z, q3.w);

        fma2(acc[0][0], q0a, ww0); fma2(acc[0][1], q0b, ww0);   // sc0
        fma2(acc[1][0], q0a, ww2); fma2(acc[1][1], q0b, ww2);   // f0
        fma2(acc[2][0], q1a, ww1); fma2(acc[2][1], q1b, ww1);   // sc1x
        fma2(acc[3][0], q2a, ww1); fma2(acc[3][1], q2b, ww1);   // sc1y
        fma2(acc[4][0], q3a, ww1); fma2(acc[4][1], q3b, ww1);   // sc1z
        fma2(acc[5][0], q1a, ww3); fma2(acc[5][1], q1b, ww3);   // f1x
        fma2(acc[6][0], q2a, ww3); fma2(acc[6][1], q2b, ww3);   // f1y
        fma2(acc[7][0], q3a, ww3); fma2(acc[7][1], q3b, ww3);   // f1z
    }
    __syncwarp();

    const float s_in = 0.17677669529663687f; // 1/sqrt(32)
    float* st = (float*)&stg[wid][0][0];

#pragma unroll
    for (int j = 0; j < 4; j++) {
        int n = base + j;
        if (n >= N) break;
        int h = j >> 1, sel = j & 1;
        float sA = node_attr[n] * s_in;

        float sc0  = pick(acc[0][h], sel) * sA;
        float f0   = pick(acc[1][h], sel) * sA;
        float sc1x = pick(acc[2][h], sel) * sA;
        float sc1y = pick(acc[3][h], sel) * sA;
        float sc1z = pick(acc[4][h], sel) * sA;
        float f1x  = pick(acc[5][h], sel) * sA;
        float f1y  = pick(acc[6][h], sel) * sA;
        float f1z  = pick(acc[7][h], sel) * sA;

        st[lane]          = sc0;
        st[32 + 3 * lane] = sc1x;
        st[33 + 3 * lane] = sc1y;
        st[34 + 3 * lane] = sc1z;
        __syncwarp();
        ((float4*)(out_node + (size_t)n * 128))[lane] = ((const float4*)st)[lane];
        __syncwarp();

        float* fb = f_buf + (size_t)n * 128;
        fb[lane]      = f0;
        fb[32 + lane] = f1x;
        fb[64 + lane] = f1y;
        fb[96 + lane] = f1z;
    }
}

// ---------------------------------------------------------------------------
// Kernel 2 (fused): per block of 128 edges:
//   GEMM1: H = sin(ES@W1*0.25) (f32x2), GEMM2: W = H@W2*0.125 (tf32 mma,
//   B fragments streamed from L1/L2 via LDG), batched message phase,
//   vector atomics, merged 4-way edge reductions.
// Dynamic smem = union region only: 17152 floats (68608 B) -> 3 blocks/SM.
// ---------------------------------------------------------------------------
#define EPAD 132
#define HP   68
#define SWS  134

__global__ void __launch_bounds__(256, 3) edge_fused_kernel(
    const int*   __restrict__ edge_src,
    const int*   __restrict__ edge_dst,
    const float* __restrict__ edge_attr,
    const float* __restrict__ edge_scalars,
    const float* __restrict__ fc_w1,
    const float* __restrict__ w_se0a,
    const float* __restrict__ w_se0b,
    const float* __restrict__ w_se1a,
    const float* __restrict__ w_se1b,
    float* __restrict__ out_edge,
    int E)
{
    extern __shared__ float sm[];
    float* region = sm;
    float* sW1  = region;                // 1024
    float* sEST = region + 1024;         // 16*132 = 2112 (k-major ES^T)
    float* sH   = region + 3136;         // 128*68 = 8704 (edge-major, tf32 bits)
    float* sW   = region;                // phase B: 128*134 = 17152

    int t = threadIdx.x;
    int e0 = blockIdx.x * 128;
    int lane = t & 31;
    int wwid = t >> 5;

    // ---- stage W1 (scaled) + ES tile ----
    {
        float4 v = ((const float4*)fc_w1)[t];
        v.x *= 0.25f; v.y *= 0.25f; v.z *= 0.25f; v.w *= 0.25f;
        ((float4*)sW1)[t] = v;
    }
#pragma unroll
    for (int r = 0; r < 2; r++) {
        int fidx = t + r * 256;     // 0..511 float4s of the ES tile
        int e = fidx >> 2;          // 0..127
        int k4 = fidx & 3;
        float4 v = make_float4(0.f, 0.f, 0.f, 0.f);
        if (e0 + e < E) v = ((const float4*)edge_scalars)[(size_t)(e0 + e) * 4 + k4];
        sEST[(k4 * 4 + 0) * EPAD + e] = v.x;
        sEST[(k4 * 4 + 1) * EPAD + e] = v.y;
        sEST[(k4 * 4 + 2) * EPAD + e] = v.z;
        sEST[(k4 * 4 + 3) * EPAD + e] = v.w;
    }
    __syncthreads();

    // ---- GEMM1: thread tile = 4 edges (2 pairs, 64 apart) x 8 cols ----
    {
        int txe = t & 31;   // edge pairs at txe*2 and txe*2+64
        int tyc = t >> 5;   // cols tyc*8 + j
        unsigned long long acc[8][2];
#pragma unroll
        for (int j = 0; j < 8; j++) { acc[j][0] = 0ull; acc[j][1] = 0ull; }
#pragma unroll
        for (int k = 0; k < 16; k++) {
            unsigned long long a0 = *(const unsigned long long*)(sEST + k * EPAD + txe * 2);
            unsigned long long a1 = *(const unsigned long long*)(sEST + k * EPAD + txe * 2 + 64);
#pragma unroll
            for (int j = 0; j < 8; j++) {
                float b = sW1[k * 64 + tyc * 8 + j];
                unsigned long long bb = pack2(b, b);
                fma2(acc[j][0], a0, bb);
                fma2(acc[j][1], a1, bb);
            }
        }
        uint32_t* sHu = (uint32_t*)sH;
#pragma unroll
        for (int j = 0; j < 8; j++) {
            int col = tyc * 8 + j;
#pragma unroll
            for (int i = 0; i < 2; i++) {
                float2 v = unpack2(acc[j][i]);
                int e = txe * 2 + 64 * i;
                sHu[e * HP + col]       = to_tf32(__sinf(v.x));
                sHu[(e + 1) * HP + col] = to_tf32(__sinf(v.y));
            }
        }
    }
    __syncthreads();

    // ---- load A fragments (16 edges per warp, K=64 -> 8 ksteps) ----
    uint32_t afr[8][4];
    {
        const uint32_t* sHu = (const uint32_t*)sH;
        int er = wwid * 16 + (lane >> 2);
        int kl = lane & 3;
#pragma unroll
        for (int ks = 0; ks < 8; ks++) {
            int k0 = ks * 8 + kl;
            afr[ks][0] = sHu[er * HP + k0];
            afr[ks][1] = sHu[(er + 8) * HP + k0];
            afr[ks][2] = sHu[er * HP + k0 + 4];
            afr[ks][3] = sHu[(er + 8) * HP + k0 + 4];
        }
    }
    __syncthreads();   // sH dead; region becomes sW

    // ---- GEMM2: tf32 mma, warp computes 16 edges x 128 outs;
    //      B fragments streamed from global (L1-resident 32KB) ----
    {
        const uint2* bf = (const uint2*)bfrag_global;
        int er = wwid * 16 + (lane >> 2);
        int nb = (lane & 3) * 2;
#pragma unroll
        for (int nt = 0; nt < 16; nt++) {
            float c0 = 0.f, c1 = 0.f, c2 = 0.f, c3 = 0.f;
#pragma unroll
            for (int ks = 0; ks < 8; ks++) {
                uint2 b = __ldg(bf + ((nt * 8 + ks) * 64 + lane * 2) / 2);
                asm volatile(
                    "mma.sync.aligned.m16n8k8.row.col.f32.tf32.tf32.f32 "
                    "{%0,%1,%2,%3},{%4,%5,%6,%7},{%8,%9},{%0,%1,%2,%3};"
                    : "+f"(c0), "+f"(c1), "+f"(c2), "+f"(c3)
                    : "r"(afr[ks][0]), "r"(afr[ks][1]), "r"(afr[ks][2]), "r"(afr[ks][3]),
                      "r"(b.x), "r"(b.y));
            }
            int n = nt * 8 + nb;
            *(float2*)(sW + er * SWS + n)       = make_float2(c0, c1);
            *(float2*)(sW + (er + 8) * SWS + n) = make_float2(c2, c3);
        }
    }
    __syncthreads();

    // ---- message phase: warp handles edges [base, base+16), batched by 4 ----
    float a0lo = w_se0a[lane],      a0hi = w_se0a[32 + lane];
    float b0lo = w_se0b[lane],      b0hi = w_se0b[32 + lane];
    float a1lo = w_se1a[lane],      a1hi = w_se1a[32 + lane];
    float b1lo = w_se1b[lane],      b1hi = w_se1b[32 + lane];

    const float INV_SQRT3 = 0.5773502691896258f;
    const float s_se   = 0.08838834764831845f;   // 1/sqrt(128)
    const float inv_nn = 0.35355339059327373f;   // 1/sqrt(8)
    const float sosc   = s_se * inv_nn;

    int base = e0 + wwid * 16;

    if (base + 16 <= E) {
        // fast path, no bounds checks
#pragma unroll 1
        for (int g = 0; g < 4; g++) {
            int   dstv[4];
            float4 eav[4];
            float g0v[4], g1xv[4], g1yv[4], g1zv[4];
            float wAv[4], wBv[4], wCv[4], wDv[4];
#pragma unroll
            for (int i = 0; i < 4; i++) {
                int eg = base + g * 4 + i;
                int el = wwid * 16 + g * 4 + i;
                int src = edge_src[eg];
                dstv[i] = edge_dst[eg];
                eav[i] = ((const float4*)edge_attr)[eg];
                const float* fr = f_buf + (size_t)src * 128;
                g0v[i]  = fr[lane];
                g1xv[i] = fr[32 + lane];
                g1yv[i] = fr[64 + lane];
                g1zv[i] = fr[96 + lane];
                const float* wr = sW + el * SWS;
                wAv[i] = wr[lane];
                wBv[i] = wr[32 + lane];
                wCv[i] = wr[64 + lane];
                wDv[i] = wr[96 + lane];
            }
#pragma unroll
            for (int i = 0; i < 4; i++) {
                float ea0 = eav[i].x, e1x = eav[i].y, e1y = eav[i].z, e1z = eav[i].w;

                float mA = wAv[i] * g0v[i] * ea0;
                float dg = g1xv[i] * e1x + g1yv[i] * e1y + g1zv[i] * e1z;
                float mD = wDv[i] * dg * INV_SQRT3;
                float gb = wBv[i] * g0v[i];
                float mBx = gb * e1x, mBy = gb * e1y, mBz = gb * e1z;
                float wCe = wCv[i] * ea0;
                float mCx = wCe * g1xv[i], mCy = wCe * g1yv[i], mCz = wCe * g1zv[i];

                float* nb = (float*)(n_buf4 + (size_t)dstv[i] * 64);
                red_v4(nb + lane * 4,       mA,  mD,  mBx, mCx);
                red_v4(nb + 128 + lane * 4, mBy, mCy, mBz, mCz);

                // merged edge-output reductions (4 instead of 6)
                float mBdot = gb * (e1x * e1x + e1y * e1y + e1z * e1z);
                float mCdot = wCe * dg;
                float v0 = (mA * a0lo + mD * a0hi) * ea0
                         + (mBdot * b0lo + mCdot * b0hi) * INV_SQRT3;
                float vC = mA * a1lo + mD * a1hi;
                float v1x = vC * e1x + (mBx * b1lo + mCx * b1hi) * ea0;
                float v1y = vC * e1y + (mBy * b1lo + mCy * b1hi) * ea0;
                float v1z = vC * e1z + (mBz * b1lo + mCz * b1hi) * ea0;

#pragma unroll
                for (int off = 16; off > 0; off >>= 1) {
                    v0  += __shfl_xor_sync(FULL, v0,  off);
                    v1x += __shfl_xor_sync(FULL, v1x, off);
                    v1y += __shfl_xor_sync(FULL, v1y, off);
                    v1z += __shfl_xor_sync(FULL, v1z, off);
                }

                if (lane == 0) {
                    float4 o;
                    o.x = ea0 + v0  * sosc;
                    o.y = e1x + v1x * sosc;
                    o.z = e1y + v1y * sosc;
                    o.w = e1z + v1z * sosc;
                    ((float4*)out_edge)[base + g * 4 + i] = o;
                }
            }
        }
    } else {
        // guarded tail path
        for (int le = 0; le < 16; le++) {
            int eg = base + le;
            if (eg >= E) break;
            int el = wwid * 16 + le;

            int src = edge_src[eg];
            int dst = edge_dst[eg];
            float4 ea = ((const float4*)edge_attr)[eg];
            float ea0 = ea.x, e1x = ea.y, e1y = ea.z, e1z = ea.w;

            const float* wr = sW + el * SWS;
            float wAs = wr[lane];
            float wBs = wr[32 + lane];
            float wCs = wr[64 + lane];
            float wDs = wr[96 + lane];

            const float* fr = f_buf + (size_t)src * 128;
            float g0  = fr[lane];
            float g1x = fr[32 + lane];
            float g1y = fr[64 + lane];
            float g1z = fr[96 + lane];

            float mA = wAs * g0 * ea0;
            float dg = g1x * e1x + g1y * e1y + g1z * e1z;
            float mD = wDs * dg * INV_SQRT3;
            float gb = wBs * g0;
            float mBx = gb * e1x, mBy = gb * e1y, mBz = gb * e1z;
            float wCe = wCs * ea0;
            float mCx = wCe * g1x, mCy = wCe * g1y, mCz = wCe * g1z;

            float* nb = (float*)(n_buf4 + (size_t)dst * 64);
            red_v4(nb + lane * 4,       mA,  mD,  mBx, mCx);
            red_v4(nb + 128 + lane * 4, mBy, mCy, mBz, mCz);

            float mBdot = gb * (e1x * e1x + e1y * e1y + e1z * e1z);
            float mCdot = wCe * dg;
            float v0 = (mA * a0lo + mD * a0hi) * ea0
                     + (mBdot * b0lo + mCdot * b0hi) * INV_SQRT3;
            float vC = mA * a1lo + mD * a1hi;
            float v1x = vC * e1x + (mBx * b1lo + mCx * b1hi) * ea0;
            float v1y = vC * e1y + (mBy * b1lo + mCy * b1hi) * ea0;
            float v1z = vC * e1z + (mBz * b1lo + mCz * b1hi) * ea0;

#pragma unroll
            for (int off = 16; off > 0; off >>= 1) {
                v0  += __shfl_xor_sync(FULL, v0,  off);
                v1x += __shfl_xor_sync(FULL, v1x, off);
                v1y += __shfl_xor_sync(FULL, v1y, off);
                v1z += __shfl_xor_sync(FULL, v1z, off);
            }

            if (lane == 0) {
                float4 o;
                o.x = ea0 + v0  * sosc;
                o.y = e1x + v1x * sosc;
                o.z = e1y + v1y * sosc;
                o.w = e1z + v1z * sosc;
                ((float4*)out_edge)[eg] = o;
            }
        }
    }
}

// ---------------------------------------------------------------------------
// Kernel 3: node post-pass. One warp per 4 nodes, f32x2-paired accumulation.
// Dynamic smem: s20(2048) s21(2048) sal(64) stg(8192 floats) = 49408 bytes.
// ---------------------------------------------------------------------------
__global__ __launch_bounds__(256) void node_post_kernel(
    const float* __restrict__ node_attr,
    const float* __restrict__ w20,
    const float* __restrict__ w21,
    const float* __restrict__ w_alpha,
    float* __restrict__ out_node,
    int N)
{
    extern __shared__ float smp[];
    float*  s20 = smp;            // 2048
    float*  s21 = smp + 2048;     // 2048
    float*  sal = smp + 4096;     // 64
    float4* stg = (float4*)(smp + 4160);  // [wid][u][half][comp]

    for (int i = threadIdx.x; i < 2048; i += blockDim.x) { s20[i] = w20[i]; s21[i] = w21[i]; }
    for (int i = threadIdx.x; i < 64; i += blockDim.x) sal[i] = w_alpha[i];
    __syncthreads();

    int warp = (blockIdx.x * blockDim.x + threadIdx.x) >> 5;
    int wid  = (threadIdx.x >> 5);
    int lane = threadIdx.x & 31;
    int base = warp * 4;
    if (base >= N) return;

    float4* stgW = stg + (size_t)wid * 32 * 2 * 4;

    // stage: half0 comps (n0a, n1ax, n1ay, n1az), half1 (n0b, n1bx, n1by, n1bz)
    {
        float4 v1[4], v2[4];
#pragma unroll
        for (int j = 0; j < 4; j++) {
            int n = min(base + j, N - 1);
            v1[j] = n_buf4[(size_t)n * 64 + lane];       // (mA,mD,mBx,mCx) sums
            v2[j] = n_buf4[(size_t)n * 64 + 32 + lane];  // (mBy,mCy,mBz,mCz) sums
        }
        float4* s = stgW + lane * 8;
        s[0] = make_float4(v1[0].x, v1[1].x, v1[2].x, v1[3].x); // n0a
        s[1] = make_float4(v1[0].z, v1[1].z, v1[2].z, v1[3].z); // n1ax
        s[2] = make_float4(v2[0].x, v2[1].x, v2[2].x, v2[3].x); // n1ay
        s[3] = make_float4(v2[0].z, v2[1].z, v2[2].z, v2[3].z); // n1az
        s[4] = make_float4(v1[0].y, v1[1].y, v1[2].y, v1[3].y); // n0b
        s[5] = make_float4(v1[0].w, v1[1].w, v1[2].w, v1[3].w); // n1bx
        s[6] = make_float4(v2[0].y, v2[1].y, v2[2].y, v2[3].y); // n1by
        s[7] = make_float4(v2[0].w, v2[1].w, v2[2].w, v2[3].w); // n1bz
    }
    __syncwarp();

    // accumulators: o0, o1x, o1y, o1z, al ; pairs (n0,n1),(n2,n3)
    unsigned long long acc[5][2];
#pragma unroll
    for (int i = 0; i < 5; i++) { acc[i][0] = 0ull; acc[i][1] = 0ull; }

#pragma unroll
    for (int u = 0; u < 32; u++) {
#pragma unroll
        for (int h = 0; h < 2; h++) {
            float wa  = s20[(u + h * 32) * 32 + lane];
            float wb  = s21[(u + h * 32) * 32 + lane];
            float wal = sal[u + h * 32];
            unsigned long long wap  = pack2(wa, wa);
            unsigned long long wbp  = pack2(wb, wb);
            unsigned long long walp = pack2(wal, wal);

            const float4* s = stgW + (u * 2 + h) * 4;
            float4 q0 = s[0];
            float4 qx = s[1];
            float4 qy = s[2];
            float4 qz = s[3];
            unsigned long long q0a = pack2(q0.x, q0.y), q0b = pack2(q0.z, q0.w);
            unsigned long long qxa = pack2(qx.x, qx.y), qxb = pack2(qx.z, qx.w);
            unsigned long long qya = pack2(qy.x, qy.y), qyb = pack2(qy.z, qy.w);
            unsigned long long qza = pack2(qz.x, qz.y), qzb = pack2(qz.z, qz.w);

            fma2(acc[0][0], q0a, wap);  fma2(acc[0][1], q0b, wap);   // o0
            fma2(acc[1][0], qxa, wbp);  fma2(acc[1][1], qxb, wbp);   // o1x
            fma2(acc[2][0], qya, wbp);  fma2(acc[2][1], qyb, wbp);   // o1y
            fma2(acc[3][0], qza, wbp);  fma2(acc[3][1], qzb, wbp);   // o1z
            fma2(acc[4][0], q0a, walp); fma2(acc[4][1], q0b, walp);  // alpha
        }
    }
    __syncwarp();

    const float s_mid  = 0.125f;                 // 1/sqrt(64)
    const float inv_nn = 0.35355339059327373f;   // 1/sqrt(8)
    float* st = (float*)stgW;

#pragma unroll
    for (int j = 0; j < 4; j++) {
        int n = base + j;
        if (n >= N) break;
        int h = j >> 1, sel = j & 1;

        float o0  = pick(acc[0][h], sel);
        float o1x = pick(acc[1][h], sel);
        float o1y = pick(acc[2][h], sel);
        float o1z = pick(acc[3][h], sel);
        float al  = pick(acc[4][h], sel);

        float sc = node_attr[n] * s_mid * inv_nn;
        float k = (al * sc) * sc;

        st[lane]          = k * o0;
        st[32 + 3 * lane] = k * o1x;
        st[33 + 3 * lane] = k * o1y;
        st[34 + 3 * lane] = k * o1z;
        __syncwarp();
        float4* on4 = (float4*)(out_node + (size_t)n * 128);
        float4 cur = on4[lane];
        float4 add = ((const float4*)st)[lane];
        cur.x += add.x; cur.y += add.y; cur.z += add.z; cur.w += add.w;
        on4[lane] = cur;
        __syncwarp();
    }
}

// ---------------------------------------------------------------------------
extern "C" void kernel_launch(void* const* d_in, const int* in_sizes, int n_in,
                              void* d_out, int out_size)
{
    const float* node_input   = (const float*)d_in[0];
    const float* node_attr    = (const float*)d_in[1];
    const int*   edge_src     = (const int*)  d_in[2];
    const int*   edge_dst     = (const int*)  d_in[3];
    const float* edge_attr    = (const float*)d_in[4];
    const float* edge_scalars = (const float*)d_in[5];
    const float* w_sc0        = (const float*)d_in[6];
    const float* w_sc1        = (const float*)d_in[7];
    const float* w_lin1_0     = (const float*)d_in[8];
    const float* w_lin1_1     = (const float*)d_in[9];
    const float* fc_w1        = (const float*)d_in[10];
    const float* fc_w2        = (const float*)d_in[11];
    const float* w_lin2_0     = (const float*)d_in[12];
    const float* w_lin2_1     = (const float*)d_in[13];
    const float* w_alpha      = (const float*)d_in[14];
    const float* w_se0a       = (const float*)d_in[15];
    const float* w_se0b       = (const float*)d_in[16];
    const float* w_se1a       = (const float*)d_in[17];
    const float* w_se1b       = (const float*)d_in[18];

    int N = in_sizes[0] / 128;
    int E = in_sizes[2];

    float* out_node = (float*)d_out;
    float* out_edge = (float*)d_out + (size_t)N * 128;

    // zero the accumulator via a captured memset node
    void* nbuf_ptr = nullptr;
    cudaGetSymbolAddress(&nbuf_ptr, n_buf4);
    cudaMemsetAsync(nbuf_ptr, 0, (size_t)N * 64 * sizeof(float4));

    const int SMEM_EDGE = 17152 * 4;          // 68608 bytes -> 3 blocks/SM
    cudaFuncSetAttribute(edge_fused_kernel,
                         cudaFuncAttributeMaxDynamicSharedMemorySize, SMEM_EDGE);
    const int SMEM_POST = (4160 + 8192) * 4;  // 49408 bytes
    cudaFuncSetAttribute(node_post_kernel,
                         cudaFuncAttributeMaxDynamicSharedMemorySize, SMEM_POST);

    prep_bfrag_kernel<<<32, 256>>>(fc_w2);

    node_pre_kernel<<<divup(N, 32), 256>>>(node_input, node_attr,
                                           w_sc0, w_sc1, w_lin1_0, w_lin1_1,
                                           out_node, N);

    edge_fused_kernel<<<divup(E, 128), 256, SMEM_EDGE>>>(
        edge_src, edge_dst, edge_attr, edge_scalars,
        fc_w1, w_se0a, w_se0b, w_se1a, w_se1b,
        out_edge, E);

    node_post_kernel<<<divup(N, 32), 256, SMEM_POST>>>(node_attr, w_lin2_0, w_lin2_1, w_alpha,
                                                       out_node, N);
}

// round 9
// speedup vs baseline: 1.3595x; 1.0457x over previous
#include <cuda_runtime.h>
#include <math.h>
#include <stdint.h>

#define FULL 0xffffffffu
#define MAXN 50000

// Scratch (device globals; no allocation allowed)
__device__ float  f_buf[MAXN * 128];      // per-node lin1 features [f0|f1x|f1y|f1z]
// per-node accum: [node][ lane*4 -> (mA,mD,mBx,mCx) | 128 + lane*4 -> (mBy,mCy,mBz,mCz) ]
__device__ float4 n_buf4[MAXN * 64];
__device__ uint32_t bfrag_global[8192];   // pre-converted tf32 B fragments of fc_w2*0.125

__host__ __device__ __forceinline__ int divup(int a, int b) { return (a + b - 1) / b; }

static __device__ __forceinline__ void red_v4(float* p, float a, float b, float c, float d) {
    asm volatile("red.global.add.v4.f32 [%0], {%1,%2,%3,%4};"
                 :: "l"(p), "f"(a), "f"(b), "f"(c), "f"(d) : "memory");
}
static __device__ __forceinline__ unsigned long long pack2(float lo, float hi) {
    unsigned long long r;
    asm("mov.b64 %0, {%1,%2};" : "=l"(r) : "f"(lo), "f"(hi));
    return r;
}
static __device__ __forceinline__ void fma2(unsigned long long& acc, unsigned long long a, unsigned long long b) {
    asm("fma.rn.f32x2 %0, %1, %2, %0;" : "+l"(acc) : "l"(a), "l"(b));
}
static __device__ __forceinline__ float2 unpack2(unsigned long long v) {
    float2 r;
    asm("mov.b64 {%0,%1}, %2;" : "=f"(r.x), "=f"(r.y) : "l"(v));
    return r;
}
static __device__ __forceinline__ float pick(unsigned long long v, int sel) {
    float2 t = unpack2(v);
    return sel ? t.y : t.x;
}
static __device__ __forceinline__ uint32_t to_tf32(float f) {
    uint32_t r; asm("cvt.rna.tf32.f32 %0, %1;" : "=r"(r) : "f"(f)); return r;
}

// ---------------------------------------------------------------------------
// One-off: convert fc_w2*0.125 into tf32 mma B-fragment layout.
// ---------------------------------------------------------------------------
__global__ __launch_bounds__(256) void prep_bfrag_kernel(const float* __restrict__ fc_w2) {
    int idx = blockIdx.x * 256 + threadIdx.x;   // 0..8191
    int n = idx & 127;
    int k = idx >> 7;
    float val = fc_w2[k * 128 + n] * 0.125f;
    int nt = n >> 3, ks = k >> 3, rb = (k >> 2) & 1;
    int ln = ((n & 7) << 2) | (k & 3);
    bfrag_global[(nt * 8 + ks) * 64 + ln * 2 + rb] = to_tf32(val);
}

// ---------------------------------------------------------------------------
// Kernel 1: node pre-pass. One warp per 4 nodes, f32x2-paired accumulation.
// Staging is comp-major: stg[wid][comp][lane] -> conflict-free stores.
// ---------------------------------------------------------------------------
__global__ __launch_bounds__(256) void node_pre_kernel(
    const float* __restrict__ node_input,
    const float* __restrict__ node_attr,
    const float* __restrict__ w_sc0,
    const float* __restrict__ w_sc1,
    const float* __restrict__ w_l0,
    const float* __restrict__ w_l1,
    float* __restrict__ out_node,
    int N)
{
    __shared__ float s0[1024], s1[1024], s2[1024], s3[1024];
    __shared__ float4 stg[8][4 * 32];   // [warp][comp*32 + lane]
    for (int i = threadIdx.x; i < 1024; i += blockDim.x) {
        s0[i] = w_sc0[i]; s1[i] = w_sc1[i]; s2[i] = w_l0[i]; s3[i] = w_l1[i];
    }
    __syncthreads();

    int warp = (blockIdx.x * blockDim.x + threadIdx.x) >> 5;
    int wid  = (threadIdx.x >> 5);
    int lane = threadIdx.x & 31;
    int base = warp * 4;
    if (base >= N) return;

    // stage 4 node rows: comp-major
    {
        float x0[4], xa[4], xb[4], xc[4];
#pragma unroll
        for (int j = 0; j < 4; j++) {
            int n = min(base + j, N - 1);
            const float* row = node_input + (size_t)n * 128;
            x0[j] = row[lane];
            xa[j] = row[32 + 3 * lane];
            xb[j] = row[33 + 3 * lane];
            xc[j] = row[34 + 3 * lane];
        }
        stg[wid][0 * 32 + lane] = make_float4(x0[0], x0[1], x0[2], x0[3]);
        stg[wid][1 * 32 + lane] = make_float4(xa[0], xa[1], xa[2], xa[3]);
        stg[wid][2 * 32 + lane] = make_float4(xb[0], xb[1], xb[2], xb[3]);
        stg[wid][3 * 32 + lane] = make_float4(xc[0], xc[1], xc[2], xc[3]);
    }
    __syncwarp();

    // accumulators: [quantity][pair]; quantities: sc0,f0,sc1x,sc1y,sc1z,f1x,f1y,f1z
    unsigned long long acc[8][2];
#pragma unroll
    for (int i = 0; i < 8; i++) { acc[i][0] = 0ull; acc[i][1] = 0ull; }

#pragma unroll
    for (int u = 0; u < 32; u++) {
        float w0 = s0[u * 32 + lane];
        float w1 = s1[u * 32 + lane];
        float w2 = s2[u * 32 + lane];
        float w3 = s3[u * 32 + lane];
        unsigned long long ww0 = pack2(w0, w0);
        unsigned long long ww1 = pack2(w1, w1);
        unsigned long long ww2 = pack2(w2, w2);
        unsigned long long ww3 = pack2(w3, w3);

        float4 q0 = stg[wid][0 * 32 + u];   // LDS.128 broadcast
        float4 q1 = stg[wid][1 * 32 + u];
        float4 q2 = stg[wid][2 * 32 + u];
        float4 q3 = stg[wid][3 * 32 + u];
        unsigned long long q0a = pack2(q0.x, q0.y), q0b = pack2(q0.z, q0.w);
        unsigned long long q1a = pack2(q1.x, q1.y), q1b = pack2(q1.z, q1.w);
        unsigned long long q2a = pack2(q2.x, q2.y), q2b = pack2(q2.z, q2.w);
        unsigned long long q3a = pack2(q3.x, q3.y), q3b = pack2(q3.z, q3.w);

        fma2(acc[0][0], q0a, ww0); fma2(acc[0][1], q0b, ww0);   // sc0
        fma2(acc[1][0], q0a, ww2); fma2(acc[1][1], q0b, ww2);   // f0
        fma2(acc[2][0], q1a, ww1); fma2(acc[2][1], q1b, ww1);   // sc1x
        fma2(acc[3][0], q2a, ww1); fma2(acc[3][1], q2b, ww1);   // sc1y
        fma2(acc[4][0], q3a, ww1); fma2(acc[4][1], q3b, ww1);   // sc1z
        fma2(acc[5][0], q1a, ww3); fma2(acc[5][1], q1b, ww3);   // f1x
        fma2(acc[6][0], q2a, ww3); fma2(acc[6][1], q2b, ww3);   // f1y
        fma2(acc[7][0], q3a, ww3); fma2(acc[7][1], q3b, ww3);   // f1z
    }
    __syncwarp();

    const float s_in = 0.17677669529663687f; // 1/sqrt(32)
    float* st = (float*)&stg[wid][0];

#pragma unroll
    for (int j = 0; j < 4; j++) {
        int n = base + j;
        if (n >= N) break;
        int h = j >> 1, sel = j & 1;
        float sA = node_attr[n] * s_in;

        float sc0  = pick(acc[0][h], sel) * sA;
        float f0   = pick(acc[1][h], sel) * sA;
        float sc1x = pick(acc[2][h], sel) * sA;
        float sc1y = pick(acc[3][h], sel) * sA;
        float sc1z = pick(acc[4][h], sel) * sA;
        float f1x  = pick(acc[5][h], sel) * sA;
        float f1y  = pick(acc[6][h], sel) * sA;
        float f1z  = pick(acc[7][h], sel) * sA;

        st[lane]          = sc0;
        st[32 + 3 * lane] = sc1x;
        st[33 + 3 * lane] = sc1y;
        st[34 + 3 * lane] = sc1z;
        __syncwarp();
        ((float4*)(out_node + (size_t)n * 128))[lane] = ((const float4*)st)[lane];
        __syncwarp();

        float* fb = f_buf + (size_t)n * 128;
        fb[lane]      = f0;
        fb[32 + lane] = f1x;
        fb[64 + lane] = f1y;
        fb[96 + lane] = f1z;
    }
}

// ---------------------------------------------------------------------------
// Kernel 2 (fused): per block of 128 edges:
//   GEMM1: H = sin(ES@W1*0.25) (f32x2), GEMM2: W = H@W2*0.125 (tf32 mma,
//   B fragments streamed from L1/L2 via LDG), batched message phase,
//   vector atomics, merged 4-way edge reductions.
// Dynamic smem = union region only: 17152 floats (68608 B) -> 3 blocks/SM.
// ---------------------------------------------------------------------------
#define EPAD 132
#define HP   68
#define SWS  134

__global__ void __launch_bounds__(256, 3) edge_fused_kernel(
    const int*   __restrict__ edge_src,
    const int*   __restrict__ edge_dst,
    const float* __restrict__ edge_attr,
    const float* __restrict__ edge_scalars,
    const float* __restrict__ fc_w1,
    const float* __restrict__ w_se0a,
    const float* __restrict__ w_se0b,
    const float* __restrict__ w_se1a,
    const float* __restrict__ w_se1b,
    float* __restrict__ out_edge,
    int E)
{
    extern __shared__ float sm[];
    float* region = sm;
    float* sW1  = region;                // 1024
    float* sEST = region + 1024;         // 16*132 = 2112 (k-major ES^T)
    float* sH   = region + 3136;         // 128*68 = 8704 (edge-major, tf32 bits)
    float* sW   = region;                // phase B: 128*134 = 17152

    int t = threadIdx.x;
    int e0 = blockIdx.x * 128;
    int lane = t & 31;
    int wwid = t >> 5;

    // ---- stage W1 (scaled) + ES tile ----
    {
        float4 v = ((const float4*)fc_w1)[t];
        v.x *= 0.25f; v.y *= 0.25f; v.z *= 0.25f; v.w *= 0.25f;
        ((float4*)sW1)[t] = v;
    }
#pragma unroll
    for (int r = 0; r < 2; r++) {
        int fidx = t + r * 256;     // 0..511 float4s of the ES tile
        int e = fidx >> 2;          // 0..127
        int k4 = fidx & 3;
        float4 v = make_float4(0.f, 0.f, 0.f, 0.f);
        if (e0 + e < E) v = ((const float4*)edge_scalars)[(size_t)(e0 + e) * 4 + k4];
        sEST[(k4 * 4 + 0) * EPAD + e] = v.x;
        sEST[(k4 * 4 + 1) * EPAD + e] = v.y;
        sEST[(k4 * 4 + 2) * EPAD + e] = v.z;
        sEST[(k4 * 4 + 3) * EPAD + e] = v.w;
    }
    __syncthreads();

    // ---- GEMM1: thread tile = 4 edges (2 pairs, 64 apart) x 8 cols ----
    {
        int txe = t & 31;   // edge pairs at txe*2 and txe*2+64
        int tyc = t >> 5;   // cols tyc*8 + j
        unsigned long long acc[8][2];
#pragma unroll
        for (int j = 0; j < 8; j++) { acc[j][0] = 0ull; acc[j][1] = 0ull; }
#pragma unroll
        for (int k = 0; k < 16; k++) {
            unsigned long long a0 = *(const unsigned long long*)(sEST + k * EPAD + txe * 2);
            unsigned long long a1 = *(const unsigned long long*)(sEST + k * EPAD + txe * 2 + 64);
#pragma unroll
            for (int j = 0; j < 8; j++) {
                float b = sW1[k * 64 + tyc * 8 + j];
                unsigned long long bb = pack2(b, b);
                fma2(acc[j][0], a0, bb);
                fma2(acc[j][1], a1, bb);
            }
        }
        uint32_t* sHu = (uint32_t*)sH;
#pragma unroll
        for (int j = 0; j < 8; j++) {
            int col = tyc * 8 + j;
#pragma unroll
            for (int i = 0; i < 2; i++) {
                float2 v = unpack2(acc[j][i]);
                int e = txe * 2 + 64 * i;
                sHu[e * HP + col]       = to_tf32(__sinf(v.x));
                sHu[(e + 1) * HP + col] = to_tf32(__sinf(v.y));
            }
        }
    }
    __syncthreads();

    // ---- load A fragments (16 edges per warp, K=64 -> 8 ksteps) ----
    uint32_t afr[8][4];
    {
        const uint32_t* sHu = (const uint32_t*)sH;
        int er = wwid * 16 + (lane >> 2);
        int kl = lane & 3;
#pragma unroll
        for (int ks = 0; ks < 8; ks++) {
            int k0 = ks * 8 + kl;
            afr[ks][0] = sHu[er * HP + k0];
            afr[ks][1] = sHu[(er + 8) * HP + k0];
            afr[ks][2] = sHu[er * HP + k0 + 4];
            afr[ks][3] = sHu[(er + 8) * HP + k0 + 4];
        }
    }
    __syncthreads();   // sH dead; region becomes sW

    // ---- GEMM2: tf32 mma, warp computes 16 edges x 128 outs;
    //      B fragments streamed from global (L1-resident 32KB) ----
    {
        const uint2* bf = (const uint2*)bfrag_global;
        int er = wwid * 16 + (lane >> 2);
        int nb = (lane & 3) * 2;
#pragma unroll
        for (int nt = 0; nt < 16; nt++) {
            float c0 = 0.f, c1 = 0.f, c2 = 0.f, c3 = 0.f;
#pragma unroll
            for (int ks = 0; ks < 8; ks++) {
                uint2 b = __ldg(bf + ((nt * 8 + ks) * 64 + lane * 2) / 2);
                asm volatile(
                    "mma.sync.aligned.m16n8k8.row.col.f32.tf32.tf32.f32 "
                    "{%0,%1,%2,%3},{%4,%5,%6,%7},{%8,%9},{%0,%1,%2,%3};"
                    : "+f"(c0), "+f"(c1), "+f"(c2), "+f"(c3)
                    : "r"(afr[ks][0]), "r"(afr[ks][1]), "r"(afr[ks][2]), "r"(afr[ks][3]),
                      "r"(b.x), "r"(b.y));
            }
            int n = nt * 8 + nb;
            *(float2*)(sW + er * SWS + n)       = make_float2(c0, c1);
            *(float2*)(sW + (er + 8) * SWS + n) = make_float2(c2, c3);
        }
    }
    __syncthreads();

    // ---- message phase: warp handles edges [base, base+16), batched by 4 ----
    float a0lo = w_se0a[lane],      a0hi = w_se0a[32 + lane];
    float b0lo = w_se0b[lane],      b0hi = w_se0b[32 + lane];
    float a1lo = w_se1a[lane],      a1hi = w_se1a[32 + lane];
    float b1lo = w_se1b[lane],      b1hi = w_se1b[32 + lane];

    const float INV_SQRT3 = 0.5773502691896258f;
    const float s_se   = 0.08838834764831845f;   // 1/sqrt(128)
    const float inv_nn = 0.35355339059327373f;   // 1/sqrt(8)
    const float sosc   = s_se * inv_nn;

    int base = e0 + wwid * 16;

    if (base + 16 <= E) {
        // fast path, no bounds checks
#pragma unroll 1
        for (int g = 0; g < 4; g++) {
            int   dstv[4];
            float4 eav[4];
            float g0v[4], g1xv[4], g1yv[4], g1zv[4];
            float wAv[4], wBv[4], wCv[4], wDv[4];
#pragma unroll
            for (int i = 0; i < 4; i++) {
                int eg = base + g * 4 + i;
                int el = wwid * 16 + g * 4 + i;
                int src = edge_src[eg];
                dstv[i] = edge_dst[eg];
                eav[i] = ((const float4*)edge_attr)[eg];
                const float* fr = f_buf + (size_t)src * 128;
                g0v[i]  = fr[lane];
                g1xv[i] = fr[32 + lane];
                g1yv[i] = fr[64 + lane];
                g1zv[i] = fr[96 + lane];
                const float* wr = sW + el * SWS;
                wAv[i] = wr[lane];
                wBv[i] = wr[32 + lane];
                wCv[i] = wr[64 + lane];
                wDv[i] = wr[96 + lane];
            }
#pragma unroll
            for (int i = 0; i < 4; i++) {
                float ea0 = eav[i].x, e1x = eav[i].y, e1y = eav[i].z, e1z = eav[i].w;

                float mA = wAv[i] * g0v[i] * ea0;
                float dg = g1xv[i] * e1x + g1yv[i] * e1y + g1zv[i] * e1z;
                float mD = wDv[i] * dg * INV_SQRT3;
                float gb = wBv[i] * g0v[i];
                float mBx = gb * e1x, mBy = gb * e1y, mBz = gb * e1z;
                float wCe = wCv[i] * ea0;
                float mCx = wCe * g1xv[i], mCy = wCe * g1yv[i], mCz = wCe * g1zv[i];

                float* nb = (float*)(n_buf4 + (size_t)dstv[i] * 64);
                red_v4(nb + lane * 4,       mA,  mD,  mBx, mCx);
                red_v4(nb + 128 + lane * 4, mBy, mCy, mBz, mCz);

                // merged edge-output reductions (4 instead of 6)
                float mBdot = gb * (e1x * e1x + e1y * e1y + e1z * e1z);
                float mCdot = wCe * dg;
                float v0 = (mA * a0lo + mD * a0hi) * ea0
                         + (mBdot * b0lo + mCdot * b0hi) * INV_SQRT3;
                float vC = mA * a1lo + mD * a1hi;
                float v1x = vC * e1x + (mBx * b1lo + mCx * b1hi) * ea0;
                float v1y = vC * e1y + (mBy * b1lo + mCy * b1hi) * ea0;
                float v1z = vC * e1z + (mBz * b1lo + mCz * b1hi) * ea0;

#pragma unroll
                for (int off = 16; off > 0; off >>= 1) {
                    v0  += __shfl_xor_sync(FULL, v0,  off);
                    v1x += __shfl_xor_sync(FULL, v1x, off);
                    v1y += __shfl_xor_sync(FULL, v1y, off);
                    v1z += __shfl_xor_sync(FULL, v1z, off);
                }

                if (lane == 0) {
                    float4 o;
                    o.x = ea0 + v0  * sosc;
                    o.y = e1x + v1x * sosc;
                    o.z = e1y + v1y * sosc;
                    o.w = e1z + v1z * sosc;
                    ((float4*)out_edge)[base + g * 4 + i] = o;
                }
            }
        }
    } else {
        // guarded tail path
        for (int le = 0; le < 16; le++) {
            int eg = base + le;
            if (eg >= E) break;
            int el = wwid * 16 + le;

            int src = edge_src[eg];
            int dst = edge_dst[eg];
            float4 ea = ((const float4*)edge_attr)[eg];
            float ea0 = ea.x, e1x = ea.y, e1y = ea.z, e1z = ea.w;

            const float* wr = sW + el * SWS;
            float wAs = wr[lane];
            float wBs = wr[32 + lane];
            float wCs = wr[64 + lane];
            float wDs = wr[96 + lane];

            const float* fr = f_buf + (size_t)src * 128;
            float g0  = fr[lane];
            float g1x = fr[32 + lane];
            float g1y = fr[64 + lane];
            float g1z = fr[96 + lane];

            float mA = wAs * g0 * ea0;
            float dg = g1x * e1x + g1y * e1y + g1z * e1z;
            float mD = wDs * dg * INV_SQRT3;
            float gb = wBs * g0;
            float mBx = gb * e1x, mBy = gb * e1y, mBz = gb * e1z;
            float wCe = wCs * ea0;
            float mCx = wCe * g1x, mCy = wCe * g1y, mCz = wCe * g1z;

            float* nb = (float*)(n_buf4 + (size_t)dst * 64);
            red_v4(nb + lane * 4,       mA,  mD,  mBx, mCx);
            red_v4(nb + 128 + lane * 4, mBy, mCy, mBz, mCz);

            float mBdot = gb * (e1x * e1x + e1y * e1y + e1z * e1z);
            float mCdot = wCe * dg;
            float v0 = (mA * a0lo + mD * a0hi) * ea0
                     + (mBdot * b0lo + mCdot * b0hi) * INV_SQRT3;
            float vC = mA * a1lo + mD * a1hi;
            float v1x = vC * e1x + (mBx * b1lo + mCx * b1hi) * ea0;
            float v1y = vC * e1y + (mBy * b1lo + mCy * b1hi) * ea0;
            float v1z = vC * e1z + (mBz * b1lo + mCz * b1hi) * ea0;

#pragma unroll
            for (int off = 16; off > 0; off >>= 1) {
                v0  += __shfl_xor_sync(FULL, v0,  off);
                v1x += __shfl_xor_sync(FULL, v1x, off);
                v1y += __shfl_xor_sync(FULL, v1y, off);
                v1z += __shfl_xor_sync(FULL, v1z, off);
            }

            if (lane == 0) {
                float4 o;
                o.x = ea0 + v0  * sosc;
                o.y = e1x + v1x * sosc;
                o.z = e1y + v1y * sosc;
                o.w = e1z + v1z * sosc;
                ((float4*)out_edge)[eg] = o;
            }
        }
    }
}

// ---------------------------------------------------------------------------
// Kernel 3: node post-pass. One warp per 4 nodes, f32x2-paired accumulation.
// Comp-major staging (conflict-free stores).
// Dynamic smem: s20(2048) s21(2048) sal(64) stg(8192 floats) = 49408 bytes.
// ---------------------------------------------------------------------------
__global__ __launch_bounds__(256) void node_post_kernel(
    const float* __restrict__ node_attr,
    const float* __restrict__ w20,
    const float* __restrict__ w21,
    const float* __restrict__ w_alpha,
    float* __restrict__ out_node,
    int N)
{
    extern __shared__ float smp[];
    float*  s20 = smp;            // 2048
    float*  s21 = smp + 2048;     // 2048
    float*  sal = smp + 4096;     // 64
    float4* stg = (float4*)(smp + 4160);  // [wid][comp 0..7][u 0..31]

    for (int i = threadIdx.x; i < 2048; i += blockDim.x) { s20[i] = w20[i]; s21[i] = w21[i]; }
    for (int i = threadIdx.x; i < 64; i += blockDim.x) sal[i] = w_alpha[i];
    __syncthreads();

    int warp = (blockIdx.x * blockDim.x + threadIdx.x) >> 5;
    int wid  = (threadIdx.x >> 5);
    int lane = threadIdx.x & 31;
    int base = warp * 4;
    if (base >= N) return;

    float4* stgW = stg + (size_t)wid * 8 * 32;

    // stage comp-major: comps 0..3 = half0 (n0a,n1ax,n1ay,n1az), 4..7 = half1
    {
        float4 v1[4], v2[4];
#pragma unroll
        for (int j = 0; j < 4; j++) {
            int n = min(base + j, N - 1);
            v1[j] = n_buf4[(size_t)n * 64 + lane];       // (mA,mD,mBx,mCx) sums
            v2[j] = n_buf4[(size_t)n * 64 + 32 + lane];  // (mBy,mCy,mBz,mCz) sums
        }
        stgW[0 * 32 + lane] = make_float4(v1[0].x, v1[1].x, v1[2].x, v1[3].x); // n0a
        stgW[1 * 32 + lane] = make_float4(v1[0].z, v1[1].z, v1[2].z, v1[3].z); // n1ax
        stgW[2 * 32 + lane] = make_float4(v2[0].x, v2[1].x, v2[2].x, v2[3].x); // n1ay
        stgW[3 * 32 + lane] = make_float4(v2[0].z, v2[1].z, v2[2].z, v2[3].z); // n1az
        stgW[4 * 32 + lane] = make_float4(v1[0].y, v1[1].y, v1[2].y, v1[3].y); // n0b
        stgW[5 * 32 + lane] = make_float4(v1[0].w, v1[1].w, v1[2].w, v1[3].w); // n1bx
        stgW[6 * 32 + lane] = make_float4(v2[0].y, v2[1].y, v2[2].y, v2[3].y); // n1by
        stgW[7 * 32 + lane] = make_float4(v2[0].w, v2[1].w, v2[2].w, v2[3].w); // n1bz
    }
    __syncwarp();

    // accumulators: o0, o1x, o1y, o1z, al ; pairs (n0,n1),(n2,n3)
    unsigned long long acc[5][2];
#pragma unroll
    for (int i = 0; i < 5; i++) { acc[i][0] = 0ull; acc[i][1] = 0ull; }

#pragma unroll
    for (int u = 0; u < 32; u++) {
#pragma unroll
        for (int h = 0; h < 2; h++) {
            float wa  = s20[(u + h * 32) * 32 + lane];
            float wb  = s21[(u + h * 32) * 32 + lane];
            float wal = sal[u + h * 32];
            unsigned long long wap  = pack2(wa, wa);
            unsigned long long wbp  = pack2(wb, wb);
            unsigned long long walp = pack2(wal, wal);

            float4 q0 = stgW[(h * 4 + 0) * 32 + u];   // broadcast LDS.128
            float4 qx = stgW[(h * 4 + 1) * 32 + u];
            float4 qy = stgW[(h * 4 + 2) * 32 + u];
            float4 qz = stgW[(h * 4 + 3) * 32 + u];
            unsigned long long q0a = pack2(q0.x, q0.y), q0b = pack2(q0.z, q0.w);
            unsigned long long qxa = pack2(qx.x, qx.y), qxb = pack2(qx.z, qx.w);
            unsigned long long qya = pack2(qy.x, qy.y), qyb = pack2(qy.z, qy.w);
            unsigned long long qza = pack2(qz.x, qz.y), qzb = pack2(qz.z, qz.w);

            fma2(acc[0][0], q0a, wap);  fma2(acc[0][1], q0b, wap);   // o0
            fma2(acc[1][0], qxa, wbp);  fma2(acc[1][1], qxb, wbp);   // o1x
            fma2(acc[2][0], qya, wbp);  fma2(acc[2][1], qyb, wbp);   // o1y
            fma2(acc[3][0], qza, wbp);  fma2(acc[3][1], qzb, wbp);   // o1z
            fma2(acc[4][0], q0a, walp); fma2(acc[4][1], q0b, walp);  // alpha
        }
    }
    __syncwarp();

    const float s_mid  = 0.125f;                 // 1/sqrt(64)
    const float inv_nn = 0.35355339059327373f;   // 1/sqrt(8)
    float* st = (float*)stgW;

#pragma unroll
    for (int j = 0; j < 4; j++) {
        int n = base + j;
        if (n >= N) break;
        int h = j >> 1, sel = j & 1;

        float o0  = pick(acc[0][h], sel);
        float o1x = pick(acc[1][h], sel);
        float o1y = pick(acc[2][h], sel);
        float o1z = pick(acc[3][h], sel);
        float al  = pick(acc[4][h], sel);

        float sc = node_attr[n] * s_mid * inv_nn;
        float k = (al * sc) * sc;

        st[lane]          = k * o0;
        st[32 + 3 * lane] = k * o1x;
        st[33 + 3 * lane] = k * o1y;
        st[34 + 3 * lane] = k * o1z;
        __syncwarp();
        float4* on4 = (float4*)(out_node + (size_t)n * 128);
        float4 cur = on4[lane];
        float4 add = ((const float4*)st)[lane];
        cur.x += add.x; cur.y += add.y; cur.z += add.z; cur.w += add.w;
        on4[lane] = cur;
        __syncwarp();
    }
}

// ---------------------------------------------------------------------------
extern "C" void kernel_launch(void* const* d_in, const int* in_sizes, int n_in,
                              void* d_out, int out_size)
{
    const float* node_input   = (const float*)d_in[0];
    const float* node_attr    = (const float*)d_in[1];
    const int*   edge_src     = (const int*)  d_in[2];
    const int*   edge_dst     = (const int*)  d_in[3];
    const float* edge_attr    = (const float*)d_in[4];
    const float* edge_scalars = (const float*)d_in[5];
    const float* w_sc0        = (const float*)d_in[6];
    const float* w_sc1        = (const float*)d_in[7];
    const float* w_lin1_0     = (const float*)d_in[8];
    const float* w_lin1_1     = (const float*)d_in[9];
    const float* fc_w1        = (const float*)d_in[10];
    const float* fc_w2        = (const float*)d_in[11];
    const float* w_lin2_0     = (const float*)d_in[12];
    const float* w_lin2_1     = (const float*)d_in[13];
    const float* w_alpha      = (const float*)d_in[14];
    const float* w_se0a       = (const float*)d_in[15];
    const float* w_se0b       = (const float*)d_in[16];
    const float* w_se1a       = (const float*)d_in[17];
    const float* w_se1b       = (const float*)d_in[18];

    int N = in_sizes[0] / 128;
    int E = in_sizes[2];

    float* out_node = (float*)d_out;
    float* out_edge = (float*)d_out + (size_t)N * 128;

    // zero the accumulator via a captured memset node
    void* nbuf_ptr = nullptr;
    cudaGetSymbolAddress(&nbuf_ptr, n_buf4);
    cudaMemsetAsync(nbuf_ptr, 0, (size_t)N * 64 * sizeof(float4));

    const int SMEM_EDGE = 17152 * 4;          // 68608 bytes -> 3 blocks/SM
    cudaFuncSetAttribute(edge_fused_kernel,
                         cudaFuncAttributeMaxDynamicSharedMemorySize, SMEM_EDGE);
    const int SMEM_POST = (4160 + 8192) * 4;  // 49408 bytes
    cudaFuncSetAttribute(node_post_kernel,
                         cudaFuncAttributeMaxDynamicSharedMemorySize, SMEM_POST);

    prep_bfrag_kernel<<<32, 256>>>(fc_w2);

    node_pre_kernel<<<divup(N, 32), 256>>>(node_input, node_attr,
                                           w_sc0, w_sc1, w_lin1_0, w_lin1_1,
                                           out_node, N);

    edge_fused_kernel<<<divup(E, 128), 256, SMEM_EDGE>>>(
        edge_src, edge_dst, edge_attr, edge_scalars,
        fc_w1, w_se0a, w_se0b, w_se1a, w_se1b,
        out_edge, E);

    node_post_kernel<<<divup(N, 32), 256, SMEM_POST>>>(node_attr, w_lin2_0, w_lin2_1, w_alpha,
                                                       out_node, N);
}

// round 10
// speedup vs baseline: 1.3644x; 1.0036x over previous
#include <cuda_runtime.h>
#include <math.h>
#include <stdint.h>

#define FULL 0xffffffffu
#define MAXN 50000

// Scratch (device globals; no allocation allowed)
__device__ float  f_buf[MAXN * 128];      // per-node lin1 features [f0|f1x|f1y|f1z]
// per-node accum: [node][ lane*4 -> (mA,mD,mBx,mCx) | 128 + lane*4 -> (mBy,mCy,mBz,mCz) ]
__device__ float4 n_buf4[MAXN * 64];
__device__ uint32_t bfrag_global[8192];   // pre-converted tf32 B fragments of fc_w2*0.125

__host__ __device__ __forceinline__ int divup(int a, int b) { return (a + b - 1) / b; }

static __device__ __forceinline__ void red_v4(float* p, float a, float b, float c, float d) {
    asm volatile("red.global.add.v4.f32 [%0], {%1,%2,%3,%4};"
                 :: "l"(p), "f"(a), "f"(b), "f"(c), "f"(d) : "memory");
}
static __device__ __forceinline__ unsigned long long pack2(float lo, float hi) {
    unsigned long long r;
    asm("mov.b64 %0, {%1,%2};" : "=l"(r) : "f"(lo), "f"(hi));
    return r;
}
static __device__ __forceinline__ void fma2(unsigned long long& acc, unsigned long long a, unsigned long long b) {
    asm("fma.rn.f32x2 %0, %1, %2, %0;" : "+l"(acc) : "l"(a), "l"(b));
}
static __device__ __forceinline__ float2 unpack2(unsigned long long v) {
    float2 r;
    asm("mov.b64 {%0,%1}, %2;" : "=f"(r.x), "=f"(r.y) : "l"(v));
    return r;
}
static __device__ __forceinline__ float pick(unsigned long long v, int sel) {
    float2 t = unpack2(v);
    return sel ? t.y : t.x;
}
static __device__ __forceinline__ uint32_t to_tf32(float f) {
    uint32_t r; asm("cvt.rna.tf32.f32 %0, %1;" : "=r"(r) : "f"(f)); return r;
}

// ---------------------------------------------------------------------------
// One-off: convert fc_w2*0.125 into tf32 mma B-fragment layout.
// ---------------------------------------------------------------------------
__global__ __launch_bounds__(256) void prep_bfrag_kernel(const float* __restrict__ fc_w2) {
    int idx = blockIdx.x * 256 + threadIdx.x;   // 0..8191
    int n = idx & 127;
    int k = idx >> 7;
    float val = fc_w2[k * 128 + n] * 0.125f;
    int nt = n >> 3, ks = k >> 3, rb = (k >> 2) & 1;
    int ln = ((n & 7) << 2) | (k & 3);
    bfrag_global[(nt * 8 + ks) * 64 + ln * 2 + rb] = to_tf32(val);
}

// ---------------------------------------------------------------------------
// Kernel 1: node pre-pass. One warp per 4 nodes, f32x2-paired accumulation.
// Staging is comp-major: stg[wid][comp][lane] -> conflict-free stores.
// ---------------------------------------------------------------------------
__global__ __launch_bounds__(256) void node_pre_kernel(
    const float* __restrict__ node_input,
    const float* __restrict__ node_attr,
    const float* __restrict__ w_sc0,
    const float* __restrict__ w_sc1,
    const float* __restrict__ w_l0,
    const float* __restrict__ w_l1,
    float* __restrict__ out_node,
    int N)
{
    __shared__ float s0[1024], s1[1024], s2[1024], s3[1024];
    __shared__ float4 stg[8][4 * 32];   // [warp][comp*32 + lane]
    for (int i = threadIdx.x; i < 1024; i += blockDim.x) {
        s0[i] = w_sc0[i]; s1[i] = w_sc1[i]; s2[i] = w_l0[i]; s3[i] = w_l1[i];
    }
    __syncthreads();

    int warp = (blockIdx.x * blockDim.x + threadIdx.x) >> 5;
    int wid  = (threadIdx.x >> 5);
    int lane = threadIdx.x & 31;
    int base = warp * 4;
    if (base >= N) return;

    // stage 4 node rows: comp-major
    {
        float x0[4], xa[4], xb[4], xc[4];
#pragma unroll
        for (int j = 0; j < 4; j++) {
            int n = min(base + j, N - 1);
            const float* row = node_input + (size_t)n * 128;
            x0[j] = row[lane];
            xa[j] = row[32 + 3 * lane];
            xb[j] = row[33 + 3 * lane];
            xc[j] = row[34 + 3 * lane];
        }
        stg[wid][0 * 32 + lane] = make_float4(x0[0], x0[1], x0[2], x0[3]);
        stg[wid][1 * 32 + lane] = make_float4(xa[0], xa[1], xa[2], xa[3]);
        stg[wid][2 * 32 + lane] = make_float4(xb[0], xb[1], xb[2], xb[3]);
        stg[wid][3 * 32 + lane] = make_float4(xc[0], xc[1], xc[2], xc[3]);
    }
    __syncwarp();

    // accumulators: [quantity][pair]; quantities: sc0,f0,sc1x,sc1y,sc1z,f1x,f1y,f1z
    unsigned long long acc[8][2];
#pragma unroll
    for (int i = 0; i < 8; i++) { acc[i][0] = 0ull; acc[i][1] = 0ull; }

#pragma unroll
    for (int u = 0; u < 32; u++) {
        float w0 = s0[u * 32 + lane];
        float w1 = s1[u * 32 + lane];
        float w2 = s2[u * 32 + lane];
        float w3 = s3[u * 32 + lane];
        unsigned long long ww0 = pack2(w0, w0);
        unsigned long long ww1 = pack2(w1, w1);
        unsigned long long ww2 = pack2(w2, w2);
        unsigned long long ww3 = pack2(w3, w3);

        float4 q0 = stg[wid][0 * 32 + u];   // LDS.128 broadcast
        float4 q1 = stg[wid][1 * 32 + u];
        float4 q2 = stg[wid][2 * 32 + u];
        float4 q3 = stg[wid][3 * 32 + u];
        unsigned long long q0a = pack2(q0.x, q0.y), q0b = pack2(q0.z, q0.w);
        unsigned long long q1a = pack2(q1.x, q1.y), q1b = pack2(q1.z, q1.w);
        unsigned long long q2a = pack2(q2.x, q2.y), q2b = pack2(q2.z, q2.w);
        unsigned long long q3a = pack2(q3.x, q3.y), q3b = pack2(q3.z, q3.w);

        fma2(acc[0][0], q0a, ww0); fma2(acc[0][1], q0b, ww0);   // sc0
        fma2(acc[1][0], q0a, ww2); fma2(acc[1][1], q0b, ww2);   // f0
        fma2(acc[2][0], q1a, ww1); fma2(acc[2][1], q1b, ww1);   // sc1x
        fma2(acc[3][0], q2a, ww1); fma2(acc[3][1], q2b, ww1);   // sc1y
        fma2(acc[4][0], q3a, ww1); fma2(acc[4][1], q3b, ww1);   // sc1z
        fma2(acc[5][0], q1a, ww3); fma2(acc[5][1], q1b, ww3);   // f1x
        fma2(acc[6][0], q2a, ww3); fma2(acc[6][1], q2b, ww3);   // f1y
        fma2(acc[7][0], q3a, ww3); fma2(acc[7][1], q3b, ww3);   // f1z
    }
    __syncwarp();

    const float s_in = 0.17677669529663687f; // 1/sqrt(32)
    float* st = (float*)&stg[wid][0];

#pragma unroll
    for (int j = 0; j < 4; j++) {
        int n = base + j;
        if (n >= N) break;
        int h = j >> 1, sel = j & 1;
        float sA = node_attr[n] * s_in;

        float sc0  = pick(acc[0][h], sel) * sA;
        float f0   = pick(acc[1][h], sel) * sA;
        float sc1x = pick(acc[2][h], sel) * sA;
        float sc1y = pick(acc[3][h], sel) * sA;
        float sc1z = pick(acc[4][h], sel) * sA;
        float f1x  = pick(acc[5][h], sel) * sA;
        float f1y  = pick(acc[6][h], sel) * sA;
        float f1z  = pick(acc[7][h], sel) * sA;

        st[lane]          = sc0;
        st[32 + 3 * lane] = sc1x;
        st[33 + 3 * lane] = sc1y;
        st[34 + 3 * lane] = sc1z;
        __syncwarp();
        ((float4*)(out_node + (size_t)n * 128))[lane] = ((const float4*)st)[lane];
        __syncwarp();

        float* fb = f_buf + (size_t)n * 128;
        fb[lane]      = f0;
        fb[32 + lane] = f1x;
        fb[64 + lane] = f1y;
        fb[96 + lane] = f1z;
    }
}

// ---------------------------------------------------------------------------
// Kernel 2 (fused): per block of 128 edges:
//   GEMM1: H = sin(ES@W1*0.25) (f32x2), GEMM2: W = H@W2*0.125 (tf32 mma,
//   B fragments streamed from L1/L2 via LDG), batched message phase,
//   vector atomics, merged 4-way edge reductions.
// Dynamic smem = union region only: 17152 floats (68608 B) -> 3 blocks/SM.
// ---------------------------------------------------------------------------
#define EPAD 132
#define HP   68
#define SWS  134

__global__ void __launch_bounds__(256, 3) edge_fused_kernel(
    const int*   __restrict__ edge_src,
    const int*   __restrict__ edge_dst,
    const float* __restrict__ edge_attr,
    const float* __restrict__ edge_scalars,
    const float* __restrict__ fc_w1,
    const float* __restrict__ w_se0a,
    const float* __restrict__ w_se0b,
    const float* __restrict__ w_se1a,
    const float* __restrict__ w_se1b,
    float* __restrict__ out_edge,
    int E)
{
    extern __shared__ float sm[];
    float* region = sm;
    float* sW1  = region;                // 1024
    float* sEST = region + 1024;         // 16*132 = 2112 (k-major ES^T)
    float* sH   = region + 3136;         // 128*68 = 8704 (edge-major, tf32 bits)
    float* sW   = region;                // phase B: 128*134 = 17152

    int t = threadIdx.x;
    int e0 = blockIdx.x * 128;
    int lane = t & 31;
    int wwid = t >> 5;

    // ---- stage W1 (scaled) + ES tile ----
    {
        float4 v = ((const float4*)fc_w1)[t];
        v.x *= 0.25f; v.y *= 0.25f; v.z *= 0.25f; v.w *= 0.25f;
        ((float4*)sW1)[t] = v;
    }
#pragma unroll
    for (int r = 0; r < 2; r++) {
        int fidx = t + r * 256;     // 0..511 float4s of the ES tile
        int e = fidx >> 2;          // 0..127
        int k4 = fidx & 3;
        float4 v = make_float4(0.f, 0.f, 0.f, 0.f);
        if (e0 + e < E) v = ((const float4*)edge_scalars)[(size_t)(e0 + e) * 4 + k4];
        sEST[(k4 * 4 + 0) * EPAD + e] = v.x;
        sEST[(k4 * 4 + 1) * EPAD + e] = v.y;
        sEST[(k4 * 4 + 2) * EPAD + e] = v.z;
        sEST[(k4 * 4 + 3) * EPAD + e] = v.w;
    }
    __syncthreads();

    // ---- GEMM1: thread tile = 4 edges (2 pairs, 64 apart) x 8 cols ----
    {
        int txe = t & 31;   // edge pairs at txe*2 and txe*2+64
        int tyc = t >> 5;   // cols tyc*8 + j
        unsigned long long acc[8][2];
#pragma unroll
        for (int j = 0; j < 8; j++) { acc[j][0] = 0ull; acc[j][1] = 0ull; }
#pragma unroll
        for (int k = 0; k < 16; k++) {
            unsigned long long a0 = *(const unsigned long long*)(sEST + k * EPAD + txe * 2);
            unsigned long long a1 = *(const unsigned long long*)(sEST + k * EPAD + txe * 2 + 64);
#pragma unroll
            for (int j = 0; j < 8; j++) {
                float b = sW1[k * 64 + tyc * 8 + j];
                unsigned long long bb = pack2(b, b);
                fma2(acc[j][0], a0, bb);
                fma2(acc[j][1], a1, bb);
            }
        }
        uint32_t* sHu = (uint32_t*)sH;
#pragma unroll
        for (int j = 0; j < 8; j++) {
            int col = tyc * 8 + j;
#pragma unroll
            for (int i = 0; i < 2; i++) {
                float2 v = unpack2(acc[j][i]);
                int e = txe * 2 + 64 * i;
                sHu[e * HP + col]       = to_tf32(__sinf(v.x));
                sHu[(e + 1) * HP + col] = to_tf32(__sinf(v.y));
            }
        }
    }
    __syncthreads();

    // ---- load A fragments (16 edges per warp, K=64 -> 8 ksteps) ----
    uint32_t afr[8][4];
    {
        const uint32_t* sHu = (const uint32_t*)sH;
        int er = wwid * 16 + (lane >> 2);
        int kl = lane & 3;
#pragma unroll
        for (int ks = 0; ks < 8; ks++) {
            int k0 = ks * 8 + kl;
            afr[ks][0] = sHu[er * HP + k0];
            afr[ks][1] = sHu[(er + 8) * HP + k0];
            afr[ks][2] = sHu[er * HP + k0 + 4];
            afr[ks][3] = sHu[(er + 8) * HP + k0 + 4];
        }
    }
    __syncthreads();   // sH dead; region becomes sW

    // ---- GEMM2: tf32 mma, warp computes 16 edges x 128 outs;
    //      B fragments streamed from global (L1-resident 32KB) ----
    {
        const uint2* bf = (const uint2*)bfrag_global;
        int er = wwid * 16 + (lane >> 2);
        int nb = (lane & 3) * 2;
#pragma unroll
        for (int nt = 0; nt < 16; nt++) {
            float c0 = 0.f, c1 = 0.f, c2 = 0.f, c3 = 0.f;
#pragma unroll
            for (int ks = 0; ks < 8; ks++) {
                uint2 b = __ldg(bf + ((nt * 8 + ks) * 64 + lane * 2) / 2);
                asm volatile(
                    "mma.sync.aligned.m16n8k8.row.col.f32.tf32.tf32.f32 "
                    "{%0,%1,%2,%3},{%4,%5,%6,%7},{%8,%9},{%0,%1,%2,%3};"
                    : "+f"(c0), "+f"(c1), "+f"(c2), "+f"(c3)
                    : "r"(afr[ks][0]), "r"(afr[ks][1]), "r"(afr[ks][2]), "r"(afr[ks][3]),
                      "r"(b.x), "r"(b.y));
            }
            int n = nt * 8 + nb;
            *(float2*)(sW + er * SWS + n)       = make_float2(c0, c1);
            *(float2*)(sW + (er + 8) * SWS + n) = make_float2(c2, c3);
        }
    }
    __syncthreads();

    // ---- message phase: warp handles edges [base, base+16), batched by 4 ----
    float a0lo = w_se0a[lane],      a0hi = w_se0a[32 + lane];
    float b0lo = w_se0b[lane],      b0hi = w_se0b[32 + lane];
    float a1lo = w_se1a[lane],      a1hi = w_se1a[32 + lane];
    float b1lo = w_se1b[lane],      b1hi = w_se1b[32 + lane];

    const float INV_SQRT3 = 0.5773502691896258f;
    const float s_se   = 0.08838834764831845f;   // 1/sqrt(128)
    const float inv_nn = 0.35355339059327373f;   // 1/sqrt(8)
    const float sosc   = s_se * inv_nn;

    int base = e0 + wwid * 16;

    if (base + 16 <= E) {
        // fast path, no bounds checks
#pragma unroll 1
        for (int g = 0; g < 4; g++) {
            int   dstv[4];
            float4 eav[4];
            float g0v[4], g1xv[4], g1yv[4], g1zv[4];
            float wAv[4], wBv[4], wCv[4], wDv[4];
#pragma unroll
            for (int i = 0; i < 4; i++) {
                int eg = base + g * 4 + i;
                int el = wwid * 16 + g * 4 + i;
                int src = edge_src[eg];
                dstv[i] = edge_dst[eg];
                eav[i] = ((const float4*)edge_attr)[eg];
                const float* fr = f_buf + (size_t)src * 128;
                g0v[i]  = fr[lane];
                g1xv[i] = fr[32 + lane];
                g1yv[i] = fr[64 + lane];
                g1zv[i] = fr[96 + lane];
                const float* wr = sW + el * SWS;
                wAv[i] = wr[lane];
                wBv[i] = wr[32 + lane];
                wCv[i] = wr[64 + lane];
                wDv[i] = wr[96 + lane];
            }
#pragma unroll
            for (int i = 0; i < 4; i++) {
                float ea0 = eav[i].x, e1x = eav[i].y, e1y = eav[i].z, e1z = eav[i].w;

                float mA = wAv[i] * g0v[i] * ea0;
                float dg = g1xv[i] * e1x + g1yv[i] * e1y + g1zv[i] * e1z;
                float mD = wDv[i] * dg * INV_SQRT3;
                float gb = wBv[i] * g0v[i];
                float mBx = gb * e1x, mBy = gb * e1y, mBz = gb * e1z;
                float wCe = wCv[i] * ea0;
                float mCx = wCe * g1xv[i], mCy = wCe * g1yv[i], mCz = wCe * g1zv[i];

                float* nb = (float*)(n_buf4 + (size_t)dstv[i] * 64);
                red_v4(nb + lane * 4,       mA,  mD,  mBx, mCx);
                red_v4(nb + 128 + lane * 4, mBy, mCy, mBz, mCz);

                // merged edge-output reductions (4 instead of 6)
                float mBdot = gb * (e1x * e1x + e1y * e1y + e1z * e1z);
                float mCdot = wCe * dg;
                float v0 = (mA * a0lo + mD * a0hi) * ea0
                         + (mBdot * b0lo + mCdot * b0hi) * INV_SQRT3;
                float vC = mA * a1lo + mD * a1hi;
                float v1x = vC * e1x + (mBx * b1lo + mCx * b1hi) * ea0;
                float v1y = vC * e1y + (mBy * b1lo + mCy * b1hi) * ea0;
                float v1z = vC * e1z + (mBz * b1lo + mCz * b1hi) * ea0;

#pragma unroll
                for (int off = 16; off > 0; off >>= 1) {
                    v0  += __shfl_xor_sync(FULL, v0,  off);
                    v1x += __shfl_xor_sync(FULL, v1x, off);
                    v1y += __shfl_xor_sync(FULL, v1y, off);
                    v1z += __shfl_xor_sync(FULL, v1z, off);
                }

                if (lane == 0) {
                    float4 o;
                    o.x = ea0 + v0  * sosc;
                    o.y = e1x + v1x * sosc;
                    o.z = e1y + v1y * sosc;
                    o.w = e1z + v1z * sosc;
                    ((float4*)out_edge)[base + g * 4 + i] = o;
                }
            }
        }
    } else {
        // guarded tail path
        for (int le = 0; le < 16; le++) {
            int eg = base + le;
            if (eg >= E) break;
            int el = wwid * 16 + le;

            int src = edge_src[eg];
            int dst = edge_dst[eg];
            float4 ea = ((const float4*)edge_attr)[eg];
            float ea0 = ea.x, e1x = ea.y, e1y = ea.z, e1z = ea.w;

            const float* wr = sW + el * SWS;
            float wAs = wr[lane];
            float wBs = wr[32 + lane];
            float wCs = wr[64 + lane];
            float wDs = wr[96 + lane];

            const float* fr = f_buf + (size_t)src * 128;
            float g0  = fr[lane];
            float g1x = fr[32 + lane];
            float g1y = fr[64 + lane];
            float g1z = fr[96 + lane];

            float mA = wAs * g0 * ea0;
            float dg = g1x * e1x + g1y * e1y + g1z * e1z;
            float mD = wDs * dg * INV_SQRT3;
            float gb = wBs * g0;
            float mBx = gb * e1x, mBy = gb * e1y, mBz = gb * e1z;
            float wCe = wCs * ea0;
            float mCx = wCe * g1x, mCy = wCe * g1y, mCz = wCe * g1z;

            float* nb = (float*)(n_buf4 + (size_t)dst * 64);
            red_v4(nb + lane * 4,       mA,  mD,  mBx, mCx);
            red_v4(nb + 128 + lane * 4, mBy, mCy, mBz, mCz);

            float mBdot = gb * (e1x * e1x + e1y * e1y + e1z * e1z);
            float mCdot = wCe * dg;
            float v0 = (mA * a0lo + mD * a0hi) * ea0
                     + (mBdot * b0lo + mCdot * b0hi) * INV_SQRT3;
            float vC = mA * a1lo + mD * a1hi;
            float v1x = vC * e1x + (mBx * b1lo + mCx * b1hi) * ea0;
            float v1y = vC * e1y + (mBy * b1lo + mCy * b1hi) * ea0;
            float v1z = vC * e1z + (mBz * b1lo + mCz * b1hi) * ea0;

#pragma unroll
            for (int off = 16; off > 0; off >>= 1) {
                v0  += __shfl_xor_sync(FULL, v0,  off);
                v1x += __shfl_xor_sync(FULL, v1x, off);
                v1y += __shfl_xor_sync(FULL, v1y, off);
                v1z += __shfl_xor_sync(FULL, v1z, off);
            }

            if (lane == 0) {
                float4 o;
                o.x = ea0 + v0  * sosc;
                o.y = e1x + v1x * sosc;
                o.z = e1y + v1y * sosc;
                o.w = e1z + v1z * sosc;
                ((float4*)out_edge)[eg] = o;
            }
        }
    }
}

// ---------------------------------------------------------------------------
// Kernel 3: node post-pass. One warp per 4 nodes, f32x2-paired accumulation.
// Comp-major staging (conflict-free stores).
// Dynamic smem: s20(2048) s21(2048) sal(64) stg(8192 floats) = 49408 bytes.
// ---------------------------------------------------------------------------
__global__ __launch_bounds__(256) void node_post_kernel(
    const float* __restrict__ node_attr,
    const float* __restrict__ w20,
    const float* __restrict__ w21,
    const float* __restrict__ w_alpha,
    float* __restrict__ out_node,
    int N)
{
    extern __shared__ float smp[];
    float*  s20 = smp;            // 2048
    float*  s21 = smp + 2048;     // 2048
    float*  sal = smp + 4096;     // 64
    float4* stg = (float4*)(smp + 4160);  // [wid][comp 0..7][u 0..31]

    for (int i = threadIdx.x; i < 2048; i += blockDim.x) { s20[i] = w20[i]; s21[i] = w21[i]; }
    for (int i = threadIdx.x; i < 64; i += blockDim.x) sal[i] = w_alpha[i];
    __syncthreads();

    int warp = (blockIdx.x * blockDim.x + threadIdx.x) >> 5;
    int wid  = (threadIdx.x >> 5);
    int lane = threadIdx.x & 31;
    int base = warp * 4;
    if (base >= N) return;

    float4* stgW = stg + (size_t)wid * 8 * 32;

    // stage comp-major: comps 0..3 = half0 (n0a,n1ax,n1ay,n1az), 4..7 = half1
    {
        float4 v1[4], v2[4];
#pragma unroll
        for (int j = 0; j < 4; j++) {
            int n = min(base + j, N - 1);
            v1[j] = n_buf4[(size_t)n * 64 + lane];       // (mA,mD,mBx,mCx) sums
            v2[j] = n_buf4[(size_t)n * 64 + 32 + lane];  // (mBy,mCy,mBz,mCz) sums
        }
        stgW[0 * 32 + lane] = make_float4(v1[0].x, v1[1].x, v1[2].x, v1[3].x); // n0a
        stgW[1 * 32 + lane] = make_float4(v1[0].z, v1[1].z, v1[2].z, v1[3].z); // n1ax
        stgW[2 * 32 + lane] = make_float4(v2[0].x, v2[1].x, v2[2].x, v2[3].x); // n1ay
        stgW[3 * 32 + lane] = make_float4(v2[0].z, v2[1].z, v2[2].z, v2[3].z); // n1az
        stgW[4 * 32 + lane] = make_float4(v1[0].y, v1[1].y, v1[2].y, v1[3].y); // n0b
        stgW[5 * 32 + lane] = make_float4(v1[0].w, v1[1].w, v1[2].w, v1[3].w); // n1bx
        stgW[6 * 32 + lane] = make_float4(v2[0].y, v2[1].y, v2[2].y, v2[3].y); // n1by
        stgW[7 * 32 + lane] = make_float4(v2[0].w, v2[1].w, v2[2].w, v2[3].w); // n1bz
    }
    __syncwarp();

    // accumulators: o0, o1x, o1y, o1z, al ; pairs (n0,n1),(n2,n3)
    unsigned long long acc[5][2];
#pragma unroll
    for (int i = 0; i < 5; i++) { acc[i][0] = 0ull; acc[i][1] = 0ull; }

#pragma unroll
    for (int u = 0; u < 32; u++) {
#pragma unroll
        for (int h = 0; h < 2; h++) {
            float wa  = s20[(u + h * 32) * 32 + lane];
            float wb  = s21[(u + h * 32) * 32 + lane];
            float wal = sal[u + h * 32];
            unsigned long long wap  = pack2(wa, wa);
            unsigned long long wbp  = pack2(wb, wb);
            unsigned long long walp = pack2(wal, wal);

            float4 q0 = stgW[(h * 4 + 0) * 32 + u];   // broadcast LDS.128
            float4 qx = stgW[(h * 4 + 1) * 32 + u];
            float4 qy = stgW[(h * 4 + 2) * 32 + u];
            float4 qz = stgW[(h * 4 + 3) * 32 + u];
            unsigned long long q0a = pack2(q0.x, q0.y), q0b = pack2(q0.z, q0.w);
            unsigned long long qxa = pack2(qx.x, qx.y), qxb = pack2(qx.z, qx.w);
            unsigned long long qya = pack2(qy.x, qy.y), qyb = pack2(qy.z, qy.w);
            unsigned long long qza = pack2(qz.x, qz.y), qzb = pack2(qz.z, qz.w);

            fma2(acc[0][0], q0a, wap);  fma2(acc[0][1], q0b, wap);   // o0
            fma2(acc[1][0], qxa, wbp);  fma2(acc[1][1], qxb, wbp);   // o1x
            fma2(acc[2][0], qya, wbp);  fma2(acc[2][1], qyb, wbp);   // o1y
            fma2(acc[3][0], qza, wbp);  fma2(acc[3][1], qzb, wbp);   // o1z
            fma2(acc[4][0], q0a, walp); fma2(acc[4][1], q0b, walp);  // alpha
        }
    }
    __syncwarp();

    const float s_mid  = 0.125f;                 // 1/sqrt(64)
    const float inv_nn = 0.35355339059327373f;   // 1/sqrt(8)
    float* st = (float*)stgW;

#pragma unroll
    for (int j = 0; j < 4; j++) {
        int n = base + j;
        if (n >= N) break;
        int h = j >> 1, sel = j & 1;

        float o0  = pick(acc[0][h], sel);
        float o1x = pick(acc[1][h], sel);
        float o1y = pick(acc[2][h], sel);
        float o1z = pick(acc[3][h], sel);
        float al  = pick(acc[4][h], sel);

        float sc = node_attr[n] * s_mid * inv_nn;
        float k = (al * sc) * sc;

        st[lane]          = k * o0;
        st[32 + 3 * lane] = k * o1x;
        st[33 + 3 * lane] = k * o1y;
        st[34 + 3 * lane] = k * o1z;
        __syncwarp();
        float4* on4 = (float4*)(out_node + (size_t)n * 128);
        float4 cur = on4[lane];
        float4 add = ((const float4*)st)[lane];
        cur.x += add.x; cur.y += add.y; cur.z += add.z; cur.w += add.w;
        on4[lane] = cur;
        __syncwarp();
    }
}

// ---------------------------------------------------------------------------
extern "C" void kernel_launch(void* const* d_in, const int* in_sizes, int n_in,
                              void* d_out, int out_size)
{
    const float* node_input   = (const float*)d_in[0];
    const float* node_attr    = (const float*)d_in[1];
    const int*   edge_src     = (const int*)  d_in[2];
    const int*   edge_dst     = (const int*)  d_in[3];
    const float* edge_attr    = (const float*)d_in[4];
    const float* edge_scalars = (const float*)d_in[5];
    const float* w_sc0        = (const float*)d_in[6];
    const float* w_sc1        = (const float*)d_in[7];
    const float* w_lin1_0     = (const float*)d_in[8];
    const float* w_lin1_1     = (const float*)d_in[9];
    const float* fc_w1        = (const float*)d_in[10];
    const float* fc_w2        = (const float*)d_in[11];
    const float* w_lin2_0     = (const float*)d_in[12];
    const float* w_lin2_1     = (const float*)d_in[13];
    const float* w_alpha      = (const float*)d_in[14];
    const float* w_se0a       = (const float*)d_in[15];
    const float* w_se0b       = (const float*)d_in[16];
    const float* w_se1a       = (const float*)d_in[17];
    const float* w_se1b       = (const float*)d_in[18];

    int N = in_sizes[0] / 128;
    int E = in_sizes[2];

    float* out_node = (float*)d_out;
    float* out_edge = (float*)d_out + (size_t)N * 128;

    // zero the accumulator via a captured memset node
    void* nbuf_ptr = nullptr;
    cudaGetSymbolAddress(&nbuf_ptr, n_buf4);
    cudaMemsetAsync(nbuf_ptr, 0, (size_t)N * 64 * sizeof(float4));

    const int SMEM_EDGE = 17152 * 4;          // 68608 bytes -> 3 blocks/SM
    cudaFuncSetAttribute(edge_fused_kernel,
                         cudaFuncAttributeMaxDynamicSharedMemorySize, SMEM_EDGE);
    const int SMEM_POST = (4160 + 8192) * 4;  // 49408 bytes
    cudaFuncSetAttribute(node_post_kernel,
                         cudaFuncAttributeMaxDynamicSharedMemorySize, SMEM_POST);

    prep_bfrag_kernel<<<32, 256>>>(fc_w2);

    node_pre_kernel<<<divup(N, 32), 256>>>(node_input, node_attr,
                                           w_sc0, w_sc1, w_lin1_0, w_lin1_1,
                                           out_node, N);

    edge_fused_kernel<<<divup(E, 128), 256, SMEM_EDGE>>>(
        edge_src, edge_dst, edge_attr, edge_scalars,
        fc_w1, w_se0a, w_se0b, w_se1a, w_se1b,
        out_edge, E);

    node_post_kernel<<<divup(N, 32), 256, SMEM_POST>>>(node_attr, w_lin2_0, w_lin2_1, w_alpha,
                                                       out_node, N);
}

// round 11
// speedup vs baseline: 1.3688x; 1.0032x over previous
#include <cuda_runtime.h>
#include <math.h>
#include <stdint.h>

#define FULL 0xffffffffu
#define MAXN 50000

// Scratch (device globals; no allocation allowed)
__device__ float  f_buf[MAXN * 128];      // per-node lin1 features [f0|f1x|f1y|f1z]
// per-node accum: [node][ lane*4 -> (mA,mD,mBx,mCx) | 128 + lane*4 -> (mBy,mCy,mBz,mCz) ]
__device__ float4 n_buf4[MAXN * 64];
__device__ uint32_t bfrag_global[8192];   // pre-converted tf32 B fragments of fc_w2*0.125

__host__ __device__ __forceinline__ int divup(int a, int b) { return (a + b - 1) / b; }

static __device__ __forceinline__ void red_v4(float* p, float a, float b, float c, float d) {
    asm volatile("red.global.add.v4.f32 [%0], {%1,%2,%3,%4};"
                 :: "l"(p), "f"(a), "f"(b), "f"(c), "f"(d) : "memory");
}
static __device__ __forceinline__ unsigned long long pack2(float lo, float hi) {
    unsigned long long r;
    asm("mov.b64 %0, {%1,%2};" : "=l"(r) : "f"(lo), "f"(hi));
    return r;
}
static __device__ __forceinline__ void fma2(unsigned long long& acc, unsigned long long a, unsigned long long b) {
    asm("fma.rn.f32x2 %0, %1, %2, %0;" : "+l"(acc) : "l"(a), "l"(b));
}
static __device__ __forceinline__ float2 unpack2(unsigned long long v) {
    float2 r;
    asm("mov.b64 {%0,%1}, %2;" : "=f"(r.x), "=f"(r.y) : "l"(v));
    return r;
}
static __device__ __forceinline__ float pick(unsigned long long v, int sel) {
    float2 t = unpack2(v);
    return sel ? t.y : t.x;
}
static __device__ __forceinline__ uint32_t to_tf32(float f) {
    uint32_t r; asm("cvt.rna.tf32.f32 %0, %1;" : "=r"(r) : "f"(f)); return r;
}

// ---------------------------------------------------------------------------
// One-off: convert fc_w2*0.125 into tf32 mma B-fragment layout.
// ---------------------------------------------------------------------------
__global__ __launch_bounds__(256) void prep_bfrag_kernel(const float* __restrict__ fc_w2) {
    int idx = blockIdx.x * 256 + threadIdx.x;   // 0..8191
    int n = idx & 127;
    int k = idx >> 7;
    float val = fc_w2[k * 128 + n] * 0.125f;
    int nt = n >> 3, ks = k >> 3, rb = (k >> 2) & 1;
    int ln = ((n & 7) << 2) | (k & 3);
    bfrag_global[(nt * 8 + ks) * 64 + ln * 2 + rb] = to_tf32(val);
}

// ---------------------------------------------------------------------------
// Kernel 1: node pre-pass. One warp per 4 nodes, f32x2-paired accumulation.
// Staging is comp-major: stg[wid][comp][lane] -> conflict-free stores.
// ---------------------------------------------------------------------------
__global__ __launch_bounds__(256) void node_pre_kernel(
    const float* __restrict__ node_input,
    const float* __restrict__ node_attr,
    const float* __restrict__ w_sc0,
    const float* __restrict__ w_sc1,
    const float* __restrict__ w_l0,
    const float* __restrict__ w_l1,
    float* __restrict__ out_node,
    int N)
{
    __shared__ float s0[1024], s1[1024], s2[1024], s3[1024];
    __shared__ float4 stg[8][4 * 32];   // [warp][comp*32 + lane]
    for (int i = threadIdx.x; i < 1024; i += blockDim.x) {
        s0[i] = w_sc0[i]; s1[i] = w_sc1[i]; s2[i] = w_l0[i]; s3[i] = w_l1[i];
    }
    __syncthreads();

    int warp = (blockIdx.x * blockDim.x + threadIdx.x) >> 5;
    int wid  = (threadIdx.x >> 5);
    int lane = threadIdx.x & 31;
    int base = warp * 4;
    if (base >= N) return;

    // stage 4 node rows: comp-major
    {
        float x0[4], xa[4], xb[4], xc[4];
#pragma unroll
        for (int j = 0; j < 4; j++) {
            int n = min(base + j, N - 1);
            const float* row = node_input + (size_t)n * 128;
            x0[j] = row[lane];
            xa[j] = row[32 + 3 * lane];
            xb[j] = row[33 + 3 * lane];
            xc[j] = row[34 + 3 * lane];
        }
        stg[wid][0 * 32 + lane] = make_float4(x0[0], x0[1], x0[2], x0[3]);
        stg[wid][1 * 32 + lane] = make_float4(xa[0], xa[1], xa[2], xa[3]);
        stg[wid][2 * 32 + lane] = make_float4(xb[0], xb[1], xb[2], xb[3]);
        stg[wid][3 * 32 + lane] = make_float4(xc[0], xc[1], xc[2], xc[3]);
    }
    __syncwarp();

    // accumulators: [quantity][pair]; quantities: sc0,f0,sc1x,sc1y,sc1z,f1x,f1y,f1z
    unsigned long long acc[8][2];
#pragma unroll
    for (int i = 0; i < 8; i++) { acc[i][0] = 0ull; acc[i][1] = 0ull; }

#pragma unroll
    for (int u = 0; u < 32; u++) {
        float w0 = s0[u * 32 + lane];
        float w1 = s1[u * 32 + lane];
        float w2 = s2[u * 32 + lane];
        float w3 = s3[u * 32 + lane];
        unsigned long long ww0 = pack2(w0, w0);
        unsigned long long ww1 = pack2(w1, w1);
        unsigned long long ww2 = pack2(w2, w2);
        unsigned long long ww3 = pack2(w3, w3);

        float4 q0 = stg[wid][0 * 32 + u];   // LDS.128 broadcast
        float4 q1 = stg[wid][1 * 32 + u];
        float4 q2 = stg[wid][2 * 32 + u];
        float4 q3 = stg[wid][3 * 32 + u];
        unsigned long long q0a = pack2(q0.x, q0.y), q0b = pack2(q0.z, q0.w);
        unsigned long long q1a = pack2(q1.x, q1.y), q1b = pack2(q1.z, q1.w);
        unsigned long long q2a = pack2(q2.x, q2.y), q2b = pack2(q2.z, q2.w);
        unsigned long long q3a = pack2(q3.x, q3.y), q3b = pack2(q3.z, q3.w);

        fma2(acc[0][0], q0a, ww0); fma2(acc[0][1], q0b, ww0);   // sc0
        fma2(acc[1][0], q0a, ww2); fma2(acc[1][1], q0b, ww2);   // f0
        fma2(acc[2][0], q1a, ww1); fma2(acc[2][1], q1b, ww1);   // sc1x
        fma2(acc[3][0], q2a, ww1); fma2(acc[3][1], q2b, ww1);   // sc1y
        fma2(acc[4][0], q3a, ww1); fma2(acc[4][1], q3b, ww1);   // sc1z
        fma2(acc[5][0], q1a, ww3); fma2(acc[5][1], q1b, ww3);   // f1x
        fma2(acc[6][0], q2a, ww3); fma2(acc[6][1], q2b, ww3);   // f1y
        fma2(acc[7][0], q3a, ww3); fma2(acc[7][1], q3b, ww3);   // f1z
    }
    __syncwarp();

    const float s_in = 0.17677669529663687f; // 1/sqrt(32)
    float* st = (float*)&stg[wid][0];

#pragma unroll
    for (int j = 0; j < 4; j++) {
        int n = base + j;
        if (n >= N) break;
        int h = j >> 1, sel = j & 1;
        float sA = node_attr[n] * s_in;

        float sc0  = pick(acc[0][h], sel) * sA;
        float f0   = pick(acc[1][h], sel) * sA;
        float sc1x = pick(acc[2][h], sel) * sA;
        float sc1y = pick(acc[3][h], sel) * sA;
        float sc1z = pick(acc[4][h], sel) * sA;
        float f1x  = pick(acc[5][h], sel) * sA;
        float f1y  = pick(acc[6][h], sel) * sA;
        float f1z  = pick(acc[7][h], sel) * sA;

        st[lane]          = sc0;
        st[32 + 3 * lane] = sc1x;
        st[33 + 3 * lane] = sc1y;
        st[34 + 3 * lane] = sc1z;
        __syncwarp();
        ((float4*)(out_node + (size_t)n * 128))[lane] = ((const float4*)st)[lane];
        __syncwarp();

        float* fb = f_buf + (size_t)n * 128;
        fb[lane]      = f0;
        fb[32 + lane] = f1x;
        fb[64 + lane] = f1y;
        fb[96 + lane] = f1z;
    }
}

// ---------------------------------------------------------------------------
// Kernel 2 (fused): per block of 128 edges:
//   GEMM1: H = sin(ES@W1*0.25) (f32x2), GEMM2: W = H@W2*0.125 (tf32 mma,
//   B fragments streamed from L1/L2 via LDG), batched message phase,
//   vector atomics, merged 4-way edge reductions.
// Dynamic smem = union region only: 17152 floats (68608 B) -> 3 blocks/SM.
// ---------------------------------------------------------------------------
#define EPAD 132
#define HP   68
#define SWS  134

__global__ void __launch_bounds__(256, 3) edge_fused_kernel(
    const int*   __restrict__ edge_src,
    const int*   __restrict__ edge_dst,
    const float* __restrict__ edge_attr,
    const float* __restrict__ edge_scalars,
    const float* __restrict__ fc_w1,
    const float* __restrict__ w_se0a,
    const float* __restrict__ w_se0b,
    const float* __restrict__ w_se1a,
    const float* __restrict__ w_se1b,
    float* __restrict__ out_edge,
    int E)
{
    extern __shared__ float sm[];
    float* region = sm;
    float* sW1  = region;                // 1024
    float* sEST = region + 1024;         // 16*132 = 2112 (k-major ES^T)
    float* sH   = region + 3136;         // 128*68 = 8704 (edge-major, tf32 bits)
    float* sW   = region;                // phase B: 128*134 = 17152

    int t = threadIdx.x;
    int e0 = blockIdx.x * 128;
    int lane = t & 31;
    int wwid = t >> 5;

    // ---- stage W1 (scaled) + ES tile ----
    {
        float4 v = ((const float4*)fc_w1)[t];
        v.x *= 0.25f; v.y *= 0.25f; v.z *= 0.25f; v.w *= 0.25f;
        ((float4*)sW1)[t] = v;
    }
#pragma unroll
    for (int r = 0; r < 2; r++) {
        int fidx = t + r * 256;     // 0..511 float4s of the ES tile
        int e = fidx >> 2;          // 0..127
        int k4 = fidx & 3;
        float4 v = make_float4(0.f, 0.f, 0.f, 0.f);
        if (e0 + e < E) v = ((const float4*)edge_scalars)[(size_t)(e0 + e) * 4 + k4];
        sEST[(k4 * 4 + 0) * EPAD + e] = v.x;
        sEST[(k4 * 4 + 1) * EPAD + e] = v.y;
        sEST[(k4 * 4 + 2) * EPAD + e] = v.z;
        sEST[(k4 * 4 + 3) * EPAD + e] = v.w;
    }
    __syncthreads();

    // ---- GEMM1: thread tile = 4 edges (2 pairs, 64 apart) x 8 cols ----
    {
        int txe = t & 31;   // edge pairs at txe*2 and txe*2+64
        int tyc = t >> 5;   // cols tyc*8 + j
        unsigned long long acc[8][2];
#pragma unroll
        for (int j = 0; j < 8; j++) { acc[j][0] = 0ull; acc[j][1] = 0ull; }
#pragma unroll
        for (int k = 0; k < 16; k++) {
            unsigned long long a0 = *(const unsigned long long*)(sEST + k * EPAD + txe * 2);
            unsigned long long a1 = *(const unsigned long long*)(sEST + k * EPAD + txe * 2 + 64);
#pragma unroll
            for (int j = 0; j < 8; j++) {
                float b = sW1[k * 64 + tyc * 8 + j];
                unsigned long long bb = pack2(b, b);
                fma2(acc[j][0], a0, bb);
                fma2(acc[j][1], a1, bb);
            }
        }
        uint32_t* sHu = (uint32_t*)sH;
#pragma unroll
        for (int j = 0; j < 8; j++) {
            int col = tyc * 8 + j;
#pragma unroll
            for (int i = 0; i < 2; i++) {
                float2 v = unpack2(acc[j][i]);
                int e = txe * 2 + 64 * i;
                sHu[e * HP + col]       = to_tf32(__sinf(v.x));
                sHu[(e + 1) * HP + col] = to_tf32(__sinf(v.y));
            }
        }
    }
    __syncthreads();

    // ---- load A fragments (16 edges per warp, K=64 -> 8 ksteps) ----
    uint32_t afr[8][4];
    {
        const uint32_t* sHu = (const uint32_t*)sH;
        int er = wwid * 16 + (lane >> 2);
        int kl = lane & 3;
#pragma unroll
        for (int ks = 0; ks < 8; ks++) {
            int k0 = ks * 8 + kl;
            afr[ks][0] = sHu[er * HP + k0];
            afr[ks][1] = sHu[(er + 8) * HP + k0];
            afr[ks][2] = sHu[er * HP + k0 + 4];
            afr[ks][3] = sHu[(er + 8) * HP + k0 + 4];
        }
    }
    __syncthreads();   // sH dead; region becomes sW

    // ---- GEMM2: tf32 mma, warp computes 16 edges x 128 outs;
    //      B fragments streamed from global (L1-resident 32KB) ----
    {
        const uint2* bf = (const uint2*)bfrag_global;
        int er = wwid * 16 + (lane >> 2);
        int nb = (lane & 3) * 2;
#pragma unroll
        for (int nt = 0; nt < 16; nt++) {
            float c0 = 0.f, c1 = 0.f, c2 = 0.f, c3 = 0.f;
#pragma unroll
            for (int ks = 0; ks < 8; ks++) {
                uint2 b = __ldg(bf + ((nt * 8 + ks) * 64 + lane * 2) / 2);
                asm volatile(
                    "mma.sync.aligned.m16n8k8.row.col.f32.tf32.tf32.f32 "
                    "{%0,%1,%2,%3},{%4,%5,%6,%7},{%8,%9},{%0,%1,%2,%3};"
                    : "+f"(c0), "+f"(c1), "+f"(c2), "+f"(c3)
                    : "r"(afr[ks][0]), "r"(afr[ks][1]), "r"(afr[ks][2]), "r"(afr[ks][3]),
                      "r"(b.x), "r"(b.y));
            }
            int n = nt * 8 + nb;
            *(float2*)(sW + er * SWS + n)       = make_float2(c0, c1);
            *(float2*)(sW + (er + 8) * SWS + n) = make_float2(c2, c3);
        }
    }
    __syncthreads();

    // ---- message phase: warp handles edges [base, base+16), batched by 4 ----
    float a0lo = w_se0a[lane],      a0hi = w_se0a[32 + lane];
    float b0lo = w_se0b[lane],      b0hi = w_se0b[32 + lane];
    float a1lo = w_se1a[lane],      a1hi = w_se1a[32 + lane];
    float b1lo = w_se1b[lane],      b1hi = w_se1b[32 + lane];

    const float INV_SQRT3 = 0.5773502691896258f;
    const float s_se   = 0.08838834764831845f;   // 1/sqrt(128)
    const float inv_nn = 0.35355339059327373f;   // 1/sqrt(8)
    const float sosc   = s_se * inv_nn;

    int base = e0 + wwid * 16;

    if (base + 16 <= E) {
        // fast path, no bounds checks
#pragma unroll 1
        for (int g = 0; g < 4; g++) {
            int   dstv[4];
            float4 eav[4];
            float g0v[4], g1xv[4], g1yv[4], g1zv[4];
            float wAv[4], wBv[4], wCv[4], wDv[4];
#pragma unroll
            for (int i = 0; i < 4; i++) {
                int eg = base + g * 4 + i;
                int el = wwid * 16 + g * 4 + i;
                int src = edge_src[eg];
                dstv[i] = edge_dst[eg];
                eav[i] = ((const float4*)edge_attr)[eg];
                const float* fr = f_buf + (size_t)src * 128;
                g0v[i]  = fr[lane];
                g1xv[i] = fr[32 + lane];
                g1yv[i] = fr[64 + lane];
                g1zv[i] = fr[96 + lane];
                const float* wr = sW + el * SWS;
                wAv[i] = wr[lane];
                wBv[i] = wr[32 + lane];
                wCv[i] = wr[64 + lane];
                wDv[i] = wr[96 + lane];
            }
#pragma unroll
            for (int i = 0; i < 4; i++) {
                float ea0 = eav[i].x, e1x = eav[i].y, e1y = eav[i].z, e1z = eav[i].w;

                float mA = wAv[i] * g0v[i] * ea0;
                float dg = g1xv[i] * e1x + g1yv[i] * e1y + g1zv[i] * e1z;
                float mD = wDv[i] * dg * INV_SQRT3;
                float gb = wBv[i] * g0v[i];
                float mBx = gb * e1x, mBy = gb * e1y, mBz = gb * e1z;
                float wCe = wCv[i] * ea0;
                float mCx = wCe * g1xv[i], mCy = wCe * g1yv[i], mCz = wCe * g1zv[i];

                float* nb = (float*)(n_buf4 + (size_t)dstv[i] * 64);
                red_v4(nb + lane * 4,       mA,  mD,  mBx, mCx);
                red_v4(nb + 128 + lane * 4, mBy, mCy, mBz, mCz);

                // merged edge-output reductions (4 instead of 6)
                float mBdot = gb * (e1x * e1x + e1y * e1y + e1z * e1z);
                float mCdot = wCe * dg;
                float v0 = (mA * a0lo + mD * a0hi) * ea0
                         + (mBdot * b0lo + mCdot * b0hi) * INV_SQRT3;
                float vC = mA * a1lo + mD * a1hi;
                float v1x = vC * e1x + (mBx * b1lo + mCx * b1hi) * ea0;
                float v1y = vC * e1y + (mBy * b1lo + mCy * b1hi) * ea0;
                float v1z = vC * e1z + (mBz * b1lo + mCz * b1hi) * ea0;

#pragma unroll
                for (int off = 16; off > 0; off >>= 1) {
                    v0  += __shfl_xor_sync(FULL, v0,  off);
                    v1x += __shfl_xor_sync(FULL, v1x, off);
                    v1y += __shfl_xor_sync(FULL, v1y, off);
                    v1z += __shfl_xor_sync(FULL, v1z, off);
                }

                if (lane == 0) {
                    float4 o;
                    o.x = ea0 + v0  * sosc;
                    o.y = e1x + v1x * sosc;
                    o.z = e1y + v1y * sosc;
                    o.w = e1z + v1z * sosc;
                    ((float4*)out_edge)[base + g * 4 + i] = o;
                }
            }
        }
    } else {
        // guarded tail path
        for (int le = 0; le < 16; le++) {
            int eg = base + le;
            if (eg >= E) break;
            int el = wwid * 16 + le;

            int src = edge_src[eg];
            int dst = edge_dst[eg];
            float4 ea = ((const float4*)edge_attr)[eg];
            float ea0 = ea.x, e1x = ea.y, e1y = ea.z, e1z = ea.w;

            const float* wr = sW + el * SWS;
            float wAs = wr[lane];
            float wBs = wr[32 + lane];
            float wCs = wr[64 + lane];
            float wDs = wr[96 + lane];

            const float* fr = f_buf + (size_t)src * 128;
            float g0  = fr[lane];
            float g1x = fr[32 + lane];
            float g1y = fr[64 + lane];
            float g1z = fr[96 + lane];

            float mA = wAs * g0 * ea0;
            float dg = g1x * e1x + g1y * e1y + g1z * e1z;
            float mD = wDs * dg * INV_SQRT3;
            float gb = wBs * g0;
            float mBx = gb * e1x, mBy = gb * e1y, mBz = gb * e1z;
            float wCe = wCs * ea0;
            float mCx = wCe * g1x, mCy = wCe * g1y, mCz = wCe * g1z;

            float* nb = (float*)(n_buf4 + (size_t)dst * 64);
            red_v4(nb + lane * 4,       mA,  mD,  mBx, mCx);
            red_v4(nb + 128 + lane * 4, mBy, mCy, mBz, mCz);

            float mBdot = gb * (e1x * e1x + e1y * e1y + e1z * e1z);
            float mCdot = wCe * dg;
            float v0 = (mA * a0lo + mD * a0hi) * ea0
                     + (mBdot * b0lo + mCdot * b0hi) * INV_SQRT3;
            float vC = mA * a1lo + mD * a1hi;
            float v1x = vC * e1x + (mBx * b1lo + mCx * b1hi) * ea0;
            float v1y = vC * e1y + (mBy * b1lo + mCy * b1hi) * ea0;
            float v1z = vC * e1z + (mBz * b1lo + mCz * b1hi) * ea0;

#pragma unroll
            for (int off = 16; off > 0; off >>= 1) {
                v0  += __shfl_xor_sync(FULL, v0,  off);
                v1x += __shfl_xor_sync(FULL, v1x, off);
                v1y += __shfl_xor_sync(FULL, v1y, off);
                v1z += __shfl_xor_sync(FULL, v1z, off);
            }

            if (lane == 0) {
                float4 o;
                o.x = ea0 + v0  * sosc;
                o.y = e1x + v1x * sosc;
                o.z = e1y + v1y * sosc;
                o.w = e1z + v1z * sosc;
                ((float4*)out_edge)[eg] = o;
            }
        }
    }
}

// ---------------------------------------------------------------------------
// Kernel 3: node post-pass. One warp per 4 nodes, f32x2-paired accumulation.
// Comp-major staging (conflict-free stores).
// Dynamic smem: s20(2048) s21(2048) sal(64) stg(8192 floats) = 49408 bytes.
// ---------------------------------------------------------------------------
__global__ __launch_bounds__(256) void node_post_kernel(
    const float* __restrict__ node_attr,
    const float* __restrict__ w20,
    const float* __restrict__ w21,
    const float* __restrict__ w_alpha,
    float* __restrict__ out_node,
    int N)
{
    extern __shared__ float smp[];
    float*  s20 = smp;            // 2048
    float*  s21 = smp + 2048;     // 2048
    float*  sal = smp + 4096;     // 64
    float4* stg = (float4*)(smp + 4160);  // [wid][comp 0..7][u 0..31]

    for (int i = threadIdx.x; i < 2048; i += blockDim.x) { s20[i] = w20[i]; s21[i] = w21[i]; }
    for (int i = threadIdx.x; i < 64; i += blockDim.x) sal[i] = w_alpha[i];
    __syncthreads();

    int warp = (blockIdx.x * blockDim.x + threadIdx.x) >> 5;
    int wid  = (threadIdx.x >> 5);
    int lane = threadIdx.x & 31;
    int base = warp * 4;
    if (base >= N) return;

    float4* stgW = stg + (size_t)wid * 8 * 32;

    // stage comp-major: comps 0..3 = half0 (n0a,n1ax,n1ay,n1az), 4..7 = half1
    {
        float4 v1[4], v2[4];
#pragma unroll
        for (int j = 0; j < 4; j++) {
            int n = min(base + j, N - 1);
            v1[j] = n_buf4[(size_t)n * 64 + lane];       // (mA,mD,mBx,mCx) sums
            v2[j] = n_buf4[(size_t)n * 64 + 32 + lane];  // (mBy,mCy,mBz,mCz) sums
        }
        stgW[0 * 32 + lane] = make_float4(v1[0].x, v1[1].x, v1[2].x, v1[3].x); // n0a
        stgW[1 * 32 + lane] = make_float4(v1[0].z, v1[1].z, v1[2].z, v1[3].z); // n1ax
        stgW[2 * 32 + lane] = make_float4(v2[0].x, v2[1].x, v2[2].x, v2[3].x); // n1ay
        stgW[3 * 32 + lane] = make_float4(v2[0].z, v2[1].z, v2[2].z, v2[3].z); // n1az
        stgW[4 * 32 + lane] = make_float4(v1[0].y, v1[1].y, v1[2].y, v1[3].y); // n0b
        stgW[5 * 32 + lane] = make_float4(v1[0].w, v1[1].w, v1[2].w, v1[3].w); // n1bx
        stgW[6 * 32 + lane] = make_float4(v2[0].y, v2[1].y, v2[2].y, v2[3].y); // n1by
        stgW[7 * 32 + lane] = make_float4(v2[0].w, v2[1].w, v2[2].w, v2[3].w); // n1bz
    }
    __syncwarp();

    // accumulators: o0, o1x, o1y, o1z, al ; pairs (n0,n1),(n2,n3)
    unsigned long long acc[5][2];
#pragma unroll
    for (int i = 0; i < 5; i++) { acc[i][0] = 0ull; acc[i][1] = 0ull; }

#pragma unroll
    for (int u = 0; u < 32; u++) {
#pragma unroll
        for (int h = 0; h < 2; h++) {
            float wa  = s20[(u + h * 32) * 32 + lane];
            float wb  = s21[(u + h * 32) * 32 + lane];
            float wal = sal[u + h * 32];
            unsigned long long wap  = pack2(wa, wa);
            unsigned long long wbp  = pack2(wb, wb);
            unsigned long long walp = pack2(wal, wal);

            float4 q0 = stgW[(h * 4 + 0) * 32 + u];   // broadcast LDS.128
            float4 qx = stgW[(h * 4 + 1) * 32 + u];
            float4 qy = stgW[(h * 4 + 2) * 32 + u];
            float4 qz = stgW[(h * 4 + 3) * 32 + u];
            unsigned long long q0a = pack2(q0.x, q0.y), q0b = pack2(q0.z, q0.w);
            unsigned long long qxa = pack2(qx.x, qx.y), qxb = pack2(qx.z, qx.w);
            unsigned long long qya = pack2(qy.x, qy.y), qyb = pack2(qy.z, qy.w);
            unsigned long long qza = pack2(qz.x, qz.y), qzb = pack2(qz.z, qz.w);

            fma2(acc[0][0], q0a, wap);  fma2(acc[0][1], q0b, wap);   // o0
            fma2(acc[1][0], qxa, wbp);  fma2(acc[1][1], qxb, wbp);   // o1x
            fma2(acc[2][0], qya, wbp);  fma2(acc[2][1], qyb, wbp);   // o1y
            fma2(acc[3][0], qza, wbp);  fma2(acc[3][1], qzb, wbp);   // o1z
            fma2(acc[4][0], q0a, walp); fma2(acc[4][1], q0b, walp);  // alpha
        }
    }
    __syncwarp();

    const float s_mid  = 0.125f;                 // 1/sqrt(64)
    const float inv_nn = 0.35355339059327373f;   // 1/sqrt(8)
    float* st = (float*)stgW;

#pragma unroll
    for (int j = 0; j < 4; j++) {
        int n = base + j;
        if (n >= N) break;
        int h = j >> 1, sel = j & 1;

        float o0  = pick(acc[0][h], sel);
        float o1x = pick(acc[1][h], sel);
        float o1y = pick(acc[2][h], sel);
        float o1z = pick(acc[3][h], sel);
        float al  = pick(acc[4][h], sel);

        float sc = node_attr[n] * s_mid * inv_nn;
        float k = (al * sc) * sc;

        st[lane]          = k * o0;
        st[32 + 3 * lane] = k * o1x;
        st[33 + 3 * lane] = k * o1y;
        st[34 + 3 * lane] = k * o1z;
        __syncwarp();
        float4* on4 = (float4*)(out_node + (size_t)n * 128);
        float4 cur = on4[lane];
        float4 add = ((const float4*)st)[lane];
        cur.x += add.x; cur.y += add.y; cur.z += add.z; cur.w += add.w;
        on4[lane] = cur;
        __syncwarp();
    }
}

// ---------------------------------------------------------------------------
extern "C" void kernel_launch(void* const* d_in, const int* in_sizes, int n_in,
                              void* d_out, int out_size)
{
    const float* node_input   = (const float*)d_in[0];
    const float* node_attr    = (const float*)d_in[1];
    const int*   edge_src     = (const int*)  d_in[2];
    const int*   edge_dst     = (const int*)  d_in[3];
    const float* edge_attr    = (const float*)d_in[4];
    const float* edge_scalars = (const float*)d_in[5];
    const float* w_sc0        = (const float*)d_in[6];
    const float* w_sc1        = (const float*)d_in[7];
    const float* w_lin1_0     = (const float*)d_in[8];
    const float* w_lin1_1     = (const float*)d_in[9];
    const float* fc_w1        = (const float*)d_in[10];
    const float* fc_w2        = (const float*)d_in[11];
    const float* w_lin2_0     = (const float*)d_in[12];
    const float* w_lin2_1     = (const float*)d_in[13];
    const float* w_alpha      = (const float*)d_in[14];
    const float* w_se0a       = (const float*)d_in[15];
    const float* w_se0b       = (const float*)d_in[16];
    const float* w_se1a       = (const float*)d_in[17];
    const float* w_se1b       = (const float*)d_in[18];

    int N = in_sizes[0] / 128;
    int E = in_sizes[2];

    float* out_node = (float*)d_out;
    float* out_edge = (float*)d_out + (size_t)N * 128;

    // zero the accumulator via a captured memset node
    void* nbuf_ptr = nullptr;
    cudaGetSymbolAddress(&nbuf_ptr, n_buf4);
    cudaMemsetAsync(nbuf_ptr, 0, (size_t)N * 64 * sizeof(float4));

    const int SMEM_EDGE = 17152 * 4;          // 68608 bytes -> 3 blocks/SM
    cudaFuncSetAttribute(edge_fused_kernel,
                         cudaFuncAttributeMaxDynamicSharedMemorySize, SMEM_EDGE);
    const int SMEM_POST = (4160 + 8192) * 4;  // 49408 bytes
    cudaFuncSetAttribute(node_post_kernel,
                         cudaFuncAttributeMaxDynamicSharedMemorySize, SMEM_POST);

    prep_bfrag_kernel<<<32, 256>>>(fc_w2);

    node_pre_kernel<<<divup(N, 32), 256>>>(node_input, node_attr,
                                           w_sc0, w_sc1, w_lin1_0, w_lin1_1,
                                           out_node, N);

    edge_fused_kernel<<<divup(E, 128), 256, SMEM_EDGE>>>(
        edge_src, edge_dst, edge_attr, edge_scalars,
        fc_w1, w_se0a, w_se0b, w_se1a, w_se1b,
        out_edge, E);

    node_post_kernel<<<divup(N, 32), 256, SMEM_POST>>>(node_attr, w_lin2_0, w_lin2_1, w_alpha,
                                                       out_node, N);
}